// round 13
// baseline (speedup 1.0000x reference)
#include <cuda_runtime.h>
#include <cuda_fp16.h>
#include <cstdint>

#define BTOK 262144
#define DM 128
#define DFF 512
#define NT 16
#define NOPS 8
#define EMB 32
#define MROWS 128
#define SLDH 136
#define MAXBLK (BTOK/MROWS + NT)
#define TSTR (BTOK + 128)

// ---------------- device scratch ----------------
__device__ float g_Lf[NOPS*NT];
__device__ float g_Lg[256*NT];
__device__ float g_Lh[256*NT];
__device__ float g_Lc[NT];
__device__ float g_Lb[NT];
__device__ double g_sabs[32];
__device__ double g_res[2];
__device__ __half g_W1h[NT*DFF*DM];   // [t][n(dff)][k(d)]
__device__ __half g_W2h[NT*DM*DFF];   // [t][nn(d)][kk(dff)]
__device__ __half g_Wch[NT*64*DFF];   // [t][n(64)][k(dff)] = s2 * W2q @ Wh1
__device__ float  g_U[NT*50*DFF];     // [t][f(49)+bias][n(dff)]
__device__ __half g_T1g[NT*256*DFF];
__device__ __half g_T1h[NT*256*DFF];
__device__ __half g_T1fc[NT*NOPS*2*DFF];
__device__ double g_sumP[NT];
__device__ int g_fill[NT];
__device__ int g_nblocks;
__device__ float g_gate[BTOK];
__device__ int g_src[NT*TSTR];
__device__ int g_bmT[MAXBLK];
__device__ int g_bmR[MAXBLK];

// ---------------- helpers ----------------
__device__ __forceinline__ uint32_t smem_u32(const void* p){
    uint32_t a;
    asm("{ .reg .u64 t; cvta.to.shared.u64 t, %1; cvt.u32.u64 %0, t; }":"=r"(a):"l"(p));
    return a;
}
__device__ __forceinline__ void ldsm4(uint32_t* r, uint32_t addr){
    asm volatile("ldmatrix.sync.aligned.m8n8.x4.shared.b16 {%0,%1,%2,%3}, [%4];"
        : "=r"(r[0]),"=r"(r[1]),"=r"(r[2]),"=r"(r[3]) : "r"(addr));
}
__device__ __forceinline__ void mma16(float* c, const uint32_t* a, const uint32_t* b){
    asm volatile("mma.sync.aligned.m16n8k16.row.col.f32.f16.f16.f32 "
        "{%0,%1,%2,%3},{%4,%5,%6,%7},{%8,%9},{%0,%1,%2,%3};"
        : "+f"(c[0]),"+f"(c[1]),"+f"(c[2]),"+f"(c[3])
        : "r"(a[0]),"r"(a[1]),"r"(a[2]),"r"(a[3]),"r"(b[0]),"r"(b[1]));
}
__device__ __forceinline__ __half2 h2pack(float a, float b){
    return __floats2half2_rn(a, b);
}
__device__ __forceinline__ void cpa16(uint32_t dst, const void* src){
    asm volatile("cp.async.cg.shared.global [%0], [%1], 16;" :: "r"(dst),"l"(src):"memory");
}
__device__ __forceinline__ void cpa_commit(){
    asm volatile("cp.async.commit_group;":::"memory");
}
__device__ __forceinline__ void cpa_wait0(){
    asm volatile("cp.async.wait_group 0;":::"memory");
}
#define BAR_SYNC2(id)   asm volatile("bar.sync %0, 256;"   :: "r"(id) : "memory")
#define BAR_ARRIVE2(id) asm volatile("bar.arrive %0, 256;" :: "r"(id) : "memory")
#define BAR_SYNC_C()    asm volatile("bar.sync 5, 128;"    ::: "memory")

// ---------------- k_lt2: init + router logit tables (1 block) ----------------
__global__ void k_lt2(const float* __restrict__ oe, const float* __restrict__ Wr,
                      const float* __restrict__ Win, const float* __restrict__ bin){
    __shared__ float WR[50*16];
    int tid = threadIdx.x;
    if (tid < NT){ g_sumP[tid]=0.0; g_fill[tid]=0; }
    if (tid < 32) g_sabs[tid]=0.0;
    if (tid < 2)  g_res[tid]=0.0;
    for (int o = tid; o < 800; o += 256){
        int f = o>>4, tt = o&15;
        const float* src = (f<49) ? (Win + f*DM) : bin;
        float acc = 0.f;
        #pragma unroll 8
        for (int d=0; d<DM; d++) acc += src[d]*Wr[d*NT+tt];
        WR[o] = acc;
    }
    __syncthreads();
    for (int o=tid; o<NOPS*NT; o+=256){
        int opv = o>>4, tt = o&15;
        float acc = 0.f;
        #pragma unroll 8
        for (int j=0;j<EMB;j++) acc += oe[opv*EMB+j]*WR[j*16+tt];
        g_Lf[o] = acc;
    }
    for (int o=tid; o<4096; o+=256){
        int av = o>>4, tt = o&15;
        float a1=0.f, a2=0.f;
        #pragma unroll
        for (int i=0;i<8;i++) if ((av>>i)&1){ a1 += WR[(32+i)*16+tt]; a2 += WR[(40+i)*16+tt]; }
        g_Lg[o]=a1; g_Lh[o]=a2;
    }
    if (tid<16){ g_Lc[tid]=WR[48*16+tid]; g_Lb[tid]=WR[49*16+tid]; }
}

// ---------------- k_scalep ----------------
__global__ void k_scalep(const float* __restrict__ W1, const float* __restrict__ W2){
    __shared__ double red[256];
    int tile = blockIdx.x >> 4;
    int sub  = blockIdx.x & 15;
    const float* W = (tile < 16 ? W1 + tile*65536 : W2 + (tile-16)*65536) + sub*4096;
    const float4* W4 = (const float4*)W;
    double s = 0.0;
    #pragma unroll
    for (int r=0;r<4;r++){
        float4 v = W4[threadIdx.x + r*256];
        s += (double)(fabsf(v.x)+fabsf(v.y)+fabsf(v.z)+fabsf(v.w));
    }
    red[threadIdx.x]=s; __syncthreads();
    for (int o=128;o;o>>=1){ if(threadIdx.x<o) red[threadIdx.x]+=red[threadIdx.x+o]; __syncthreads(); }
    if (!threadIdx.x) atomicAdd(&g_sabs[tile], red[0]);
}

// ---------------- k_quant ----------------
__global__ void k_quant(const float* __restrict__ W1, const float* __restrict__ W2){
    __shared__ __half sh[64*130];
    __shared__ double red[256];
    int b = blockIdx.x, tid = threadIdx.x;
    double racc = 0.0;
    if (b < 128){
        int t = b>>3, n0 = (b&7)*64;
        float s = (float)(g_sabs[t]/65536.0);
        const float* src = W1 + t*65536;
        #pragma unroll
        for (int j=0;j<32;j++){
            int i = tid + j*256;
            int k = i>>6, nx = i&63;
            float w = src[k*512 + n0 + nx];
            float aw = fabsf(w);
            bool nz = aw > 0.7f*s;
            float q = nz ? (w>0.f?1.f:-1.f) : 0.f;
            racc += (double)(nz ? fabsf(aw - s) : aw);
            sh[nx*130 + k] = __float2half(q);
        }
        __syncthreads();
        __half* dst = g_W1h + t*65536 + n0*128;
        #pragma unroll
        for (int j=0;j<32;j++){
            int i = tid + j*256;
            int n = i>>7, k = i&127;
            dst[n*128 + k] = sh[n*130 + k];
        }
        red[tid]=racc; __syncthreads();
        for(int o=128;o;o>>=1){ if(tid<o) red[tid]+=red[tid+o]; __syncthreads(); }
        if (!tid) atomicAdd(&g_res[0], red[0]);
    } else {
        int bb = b-128;
        int t = bb>>3, kk0 = (bb&7)*64;
        float s = (float)(g_sabs[16+t]/65536.0);
        const float* src = W2 + t*65536;
        #pragma unroll
        for (int j=0;j<32;j++){
            int i = tid + j*256;
            int kk = i>>7, nn = i&127;
            float w = src[(kk0+kk)*128 + nn];
            float aw = fabsf(w);
            bool nz = aw > 0.7f*s;
            float q = nz ? (w>0.f?1.f:-1.f) : 0.f;
            racc += (double)(nz ? fabsf(aw - s) : aw);
            sh[kk*130 + nn] = __float2half(q);
        }
        __syncthreads();
        __half* dst = g_W2h + t*65536 + kk0;
        #pragma unroll
        for (int j=0;j<32;j++){
            int i = tid + j*256;
            int nn = i>>6, kx = i&63;
            dst[nn*512 + kx] = sh[kx*130 + nn];
        }
        red[tid]=racc; __syncthreads();
        for(int o=128;o;o>>=1){ if(tid<o) red[tid]+=red[tid+o]; __syncthreads(); }
        if (!tid) atomicAdd(&g_res[1], red[0]);
    }
}

// ---------------- k_u: U = [Win;bin] @ W1q^T per tile ----------------
__global__ void k_u(const float* __restrict__ Win, const float* __restrict__ bin){
    __shared__ float sWin[50*128];
    __shared__ __half sW[64*128];
    int b = blockIdx.x, tid = threadIdx.x;
    int t = b>>3, n0 = (b&7)*64;
    for (int i=tid; i<6400; i+=256) sWin[i] = (i<6272) ? Win[i] : bin[i-6272];
    const __half* src = g_W1h + t*65536 + n0*128;
    #pragma unroll
    for (int j=0;j<32;j++) sW[tid + j*256] = src[tid + j*256];
    __syncthreads();
    for (int o=tid; o<3200; o+=256){
        int f = o>>6, n = o&63;
        float acc = 0.f;
        #pragma unroll 8
        for (int d=0; d<128; d++)
            acc += sWin[f*128+d] * __half2float(sW[n*128+d]);
        g_U[(t*50+f)*512 + n0 + n] = acc;
    }
}

// ---------------- k_prep: merged tg(0-255) | wc(256-511) | tfc(512-527) ----------------
__global__ void k_prep(const float* __restrict__ Wh1, const float* __restrict__ oe){
    __shared__ char buf[41984];
    int b = blockIdx.x, tid = threadIdx.x;
    if (b < 256){
        float* sU = (float*)buf;                 // 8*512 floats = 16KB
        int t = b>>4, which = (b>>3)&1, av0 = (b&7)*32;
        for (int i=tid; i<4096; i+=256)
            sU[i] = g_U[(t*50 + 32 + which*8 + (i>>9))*512 + (i&511)];
        float s1 = (float)(g_sabs[t]/65536.0);
        __half* dst = (which ? g_T1h : g_T1g) + ((size_t)t<<17) + (size_t)av0*512;
        __syncthreads();
        for (int o=tid; o<16384; o+=256){
            int av = av0 + (o>>9), n = o&511;
            float acc = 0.f;
            #pragma unroll
            for (int i=0;i<8;i++) if ((av>>i)&1) acc += sU[i*512+n];
            dst[o] = __float2half(s1*acc);
        }
    } else if (b < 512){
        float* sWh1 = (float*)buf;               // 128*64 floats = 32KB
        __half* sW2 = (__half*)(buf + 32768);    // 128*32 halves = 8KB
        int bb = b-256;
        int t = bb>>4, k0 = (bb&15)*32;
        float s2 = (float)(g_sabs[16+t]/65536.0);
        #pragma unroll
        for (int j=0;j<32;j++) sWh1[tid + j*256] = Wh1[tid + j*256];
        const __half* W2p = g_W2h + t*65536 + k0;
        #pragma unroll
        for (int j=0;j<16;j++){
            int i = tid + j*256;
            int d = i>>5, kx = i&31;
            sW2[d*32 + kx] = W2p[d*512 + kx];
        }
        __syncthreads();
        #pragma unroll
        for (int j=0;j<8;j++){
            int o = tid + j*256;
            int n = o&63, kx = o>>6;
            float acc = 0.f;
            #pragma unroll 8
            for (int d=0; d<128; d++)
                acc += __half2float(sW2[d*32 + kx]) * sWh1[d*64 + n];
            g_Wch[t*32768 + n*512 + k0 + kx] = __float2half(s2*acc);
        }
    } else {
        int t = b-512;
        float s1 = (float)(g_sabs[t]/65536.0);
        for (int o=tid; o<8192; o+=256){
            int n = o&511, cc = (o>>9)&1, opv = o>>10;
            float acc = g_U[(t*50+49)*512+n];
            if (cc) acc += g_U[(t*50+48)*512+n];
            #pragma unroll 8
            for (int j=0;j<32;j++)
                acc += oe[opv*32+j] * g_U[(t*50+j)*512+n];
            g_T1fc[t*8192 + o] = __float2half(s1*acc);
        }
    }
}

// ---------------- k_route ----------------
__global__ void k_route(const int* __restrict__ op, const int* __restrict__ a,
                        const int* __restrict__ b, const int* __restrict__ c,
                        float* __restrict__ outIdx){
    __shared__ float sLf[NOPS*NT], sLg[256*NT], sLh[256*NT], sLc[NT], sLb[NT];
    __shared__ float sP[NT]; __shared__ int sC[NT]; __shared__ int sBase[NT];
    int tid = threadIdx.x;
    int lane = tid & 31;
    for (int i=tid;i<256*NT;i+=256){ sLg[i]=g_Lg[i]; sLh[i]=g_Lh[i]; }
    for (int i=tid;i<NOPS*NT;i+=256) sLf[i]=g_Lf[i];
    if (tid<NT){ sLc[tid]=g_Lc[tid]; sLb[tid]=g_Lb[tid]; sP[tid]=0.f; sC[tid]=0; }
    __syncthreads();
    int i = blockIdx.x*256+tid;
    int opv=op[i], av=a[i], bv=b[i]; float cv=(float)c[i];
    float l[NT]; float mx=-1e30f; int best=0;
    #pragma unroll
    for (int t=0;t<NT;t++){
        float v = sLf[opv*NT+t]+sLg[av*NT+t]+sLh[bv*NT+t]+cv*sLc[t]+sLb[t];
        l[t]=v;
        if (v>mx){mx=v;best=t;}
    }
    float den=0.f;
    #pragma unroll
    for (int t=0;t<NT;t++){ l[t]=__expf(l[t]-mx); den+=l[t]; }
    float inv = 1.f/den;
    #pragma unroll
    for (int t=0;t<NT;t++){
        float v = l[t]*inv;
        #pragma unroll
        for (int o=16;o;o>>=1) v += __shfl_xor_sync(0xffffffffu, v, o);
        if (lane==0) atomicAdd(&sP[t], v);
    }
    int rank = atomicAdd(&sC[best], 1);
    g_gate[i]=inv; outIdx[i]=(float)best;
    __syncthreads();
    if (tid<NT){
        sBase[tid] = atomicAdd(&g_fill[tid], sC[tid]);
        atomicAdd(&g_sumP[tid], (double)sP[tid]);
    }
    __syncthreads();
    g_src[best*TSTR + sBase[best] + rank] = i;
}

// ---------------- k_part (+ fused aux) ----------------
__global__ void k_part(float* __restrict__ aux){
    __shared__ int pc[NT], po_[NT];
    int tid=threadIdx.x;
    if (tid<NT) pc[tid] = g_fill[tid];
    __syncthreads();
    if (tid==0){
        int nb=0;
        for (int t=0;t<NT;t++){ po_[t]=nb; nb += (pc[t]+MROWS-1)/MROWS; }
        g_nblocks = nb;
    }
    if (tid==32){
        double sp=0.0, cp[4]={0,0,0,0};
        for (int t=0;t<NT;t++){
            double frac = (double)g_fill[t]/(double)BTOK;
            double mp = g_sumP[t]/(double)BTOK;
            sp += frac*mp;
            cp[t>>2] += mp;
        }
        double sparsity = 16.0*sp;
        double tern = g_res[0]/1048576.0 + g_res[1]/1048576.0;
        double divv = 0.0;
        for (int i=0;i<4;i++) divv += cp[i]*log(cp[i]+1e-9);
        aux[0] = (float)(0.01*tern + 0.005*sparsity + 0.01*divv);
    }
    __syncthreads();
    for (int t=0;t<NT;t++){
        int bl = (pc[t]+MROWS-1)/MROWS;
        for (int bi=tid; bi<bl; bi+=256){ g_bmT[po_[t]+bi]=t; g_bmR[po_[t]+bi]=t*TSTR + bi*MROWS; }
        int cnt=pc[t]; int pad = bl*MROWS;
        for (int p=cnt+tid; p<pad; p+=256) g_src[t*TSTR+p] = -1;
    }
}

// ---------------- k_ffn: warp-specialized producer/consumer ----------------
__global__ void __launch_bounds__(256,2) k_ffn(
    const int* __restrict__ op, const int* __restrict__ aIn,
    const int* __restrict__ bIn, const int* __restrict__ cIn,
    const float* __restrict__ bh1,
    const float* __restrict__ Wh2, const float* __restrict__ bh2,
    float* __restrict__ outR)
{
    extern __shared__ __half sm[];
    __half* sG0 = sm;                       // [128][SLDH]
    __half* sG1 = sm + 128*SLDH;            // [128][SLDH]
    __half* sW0 = sm + 256*SLDH;            // [64][SLDH]
    __half* sW1 = sW0 + 64*SLDH;            // [64][SLDH]
    __shared__ float sGate[MROWS];
    __shared__ int   sSrc[MROWS];
    __shared__ int   sAV[MROWS], sBV[MROWS], sOC[MROWS];
    __shared__ float sWh2[512], sbh1[64], sbh2[8];

    int bid = blockIdx.x;
    if (bid >= g_nblocks) return;
    int t  = g_bmT[bid], r0 = g_bmR[bid];
    int tid = threadIdx.x;
    int wid = tid>>5, lane = tid&31;

    if (tid < 128){
        int token = g_src[r0+tid];
        sSrc[tid] = token;
        if (token>=0){
            sGate[tid] = g_gate[token];
            sAV[tid] = aIn[token];
            sBV[tid] = bIn[token];
            sOC[tid] = (t*8 + op[token])*2 + cIn[token];
        } else {
            sGate[tid]=0.f; sAV[tid]=0; sBV[tid]=0; sOC[tid]=t*16;
        }
    }
    for (int i=tid;i<512;i+=256) sWh2[i]=Wh2[i];
    if (tid<64) sbh1[tid]=bh1[tid];
    if (tid<8)  sbh2[tid]=bh2[tid];
    __syncthreads();

    uint32_t gbuf[2] = { smem_u32(sG0), smem_u32(sG1) };
    uint32_t wbuf[2] = { smem_u32(sW0), smem_u32(sW1) };

    if (wid < 4){
        // ================= PRODUCER =================
        int lt4 = lane>>3, lc8 = lane&7;
        const __half2 C0 = __floats2half2_rn(0.044715f, 0.044715f);
        const __half2 C1 = __floats2half2_rn(0.7978845608f, 0.7978845608f);
        const __half2 ONE = __floats2half2_rn(1.f, 1.f);
        const __half2 HLF = __floats2half2_rn(0.5f, 0.5f);
        for (int ch=0; ch<4; ch++){
            int buf = ch&1;
            if (ch>=2) BAR_SYNC2(3+buf);
            __half* gdst = buf ? sG1 : sG0;
            #pragma unroll
            for (int it=0; it<8; it++){
                int row = wid*32 + it*4 + lt4;
                int token = sSrc[row];
                __half* dst = gdst + row*SLDH + lc8*8;
                if (token>=0){
                    const __half* pg = g_T1g + ((((size_t)(t<<8)+sAV[row])<<9) + ch*128 + lc8*8);
                    const __half* ph = g_T1h + ((((size_t)(t<<8)+sBV[row])<<9) + ch*128 + lc8*8);
                    const __half* pf = g_T1fc + (((size_t)sOC[row]<<9) + ch*128 + lc8*8);
                    #pragma unroll
                    for (int seg=0; seg<2; seg++){
                        int off = seg*64;
                        uint4 va = *(const uint4*)(pg+off);
                        uint4 vb = *(const uint4*)(ph+off);
                        uint4 vf = *(const uint4*)(pf+off);
                        __half2* ha=(__half2*)&va;
                        __half2* hb=(__half2*)&vb;
                        __half2* hf=(__half2*)&vf;
                        uint4 ou; __half2* ho=(__half2*)&ou;
                        #pragma unroll
                        for (int q=0;q<4;q++){
                            __half2 v  = __hadd2(__hadd2(ha[q],hb[q]), hf[q]);
                            __half2 v2 = __hmul2(v,v);
                            __half2 v3 = __hmul2(v2,v);
                            __half2 in2= __hfma2(v3, C0, v);
                            __half2 u  = __hmul2(in2, C1);
                            uint32_t ur = *(uint32_t*)&u, tr;
                            asm("tanh.approx.f16x2 %0, %1;" : "=r"(tr) : "r"(ur));
                            __half2 th = *(__half2*)&tr;
                            __half2 onep = __hadd2(th, ONE);
                            __half2 hv = __hmul2(v, HLF);
                            ho[q] = __hmul2(hv, onep);
                        }
                        *(uint4*)(dst+off) = ou;
                    }
                } else {
                    uint4 z = make_uint4(0,0,0,0);
                    *(uint4*)(dst) = z;
                    *(uint4*)(dst+64) = z;
                }
            }
            BAR_ARRIVE2(1+buf);
        }
    } else {
        // ================= CONSUMER =================
        int cm = wid-4;
        int ctid = cm*32 + lane;
        int grp = lane>>2, tq = lane&3;
        uint32_t aoff  = (uint32_t)((lane&15)*SLDH + (lane>>4)*8)*2;
        uint32_t boff4 = (uint32_t)(((lane&7) + ((lane>>4)<<3))*SLDH + ((lane>>3)&1)*8)*2;
        const __half* Wcp = g_Wch + t*32768;

        #pragma unroll
        for (int j=0;j<8;j++){
            int i = ctid + j*128;
            int row = i>>4, ck = i&15;
            cpa16(wbuf[0] + (uint32_t)(row*SLDH + ck*8)*2, Wcp + row*512 + ck*8);
        }
        cpa_commit();

        float c2[2][8][4];
        #pragma unroll
        for(int mt=0;mt<2;mt++)
            #pragma unroll
            for(int nt=0;nt<8;nt++)
                #pragma unroll
                for(int e=0;e<4;e++) c2[mt][nt][e]=0.f;

        for (int ch=0; ch<4; ch++){
            int buf = ch&1;
            cpa_wait0();
            BAR_SYNC_C();
            BAR_SYNC2(1+buf);
            if (ch<3){
                const __half* src = Wcp + (ch+1)*128;
                #pragma unroll
                for (int j=0;j<8;j++){
                    int i = ctid + j*128;
                    int row = i>>4, ck = i&15;
                    cpa16(wbuf[(ch+1)&1] + (uint32_t)(row*SLDH + ck*8)*2, src + row*512 + ck*8);
                }
                cpa_commit();
            }
            uint32_t bg = gbuf[buf], bw = wbuf[buf];
            #pragma unroll
            for (int kk=0;kk<8;kk++){
                uint32_t af[2][4];
                ldsm4(af[0], bg + aoff + (uint32_t)((cm*32)*SLDH + kk*16)*2);
                ldsm4(af[1], bg + aoff + (uint32_t)((cm*32+16)*SLDH + kk*16)*2);
                #pragma unroll
                for (int ntp=0;ntp<4;ntp++){
                    uint32_t bq[4];
                    ldsm4(bq, bw + boff4 + (uint32_t)((ntp*16)*SLDH + kk*16)*2);
                    mma16(c2[0][2*ntp],   af[0], bq);
                    mma16(c2[1][2*ntp],   af[1], bq);
                    mma16(c2[0][2*ntp+1], af[0], bq+2);
                    mma16(c2[1][2*ntp+1], af[1], bq+2);
                }
            }
            if (ch<2) BAR_ARRIVE2(3+buf);
        }

        // ---- epilogue: h = relu(gate*c2 + bh1) -> sH (overwrites sG0) ----
        float* sH = (float*)sG0;   // [128][66]
        #pragma unroll
        for (int mt=0;mt<2;mt++){
            int row0 = cm*32+mt*16+grp;
            float ga = sGate[row0], gb = sGate[row0+8];
            #pragma unroll
            for (int nt=0;nt<8;nt++){
                int col = nt*8+2*tq;
                sH[row0*66+col]       = fmaxf(ga*c2[mt][nt][0]+sbh1[col],   0.f);
                sH[row0*66+col+1]     = fmaxf(ga*c2[mt][nt][1]+sbh1[col+1], 0.f);
                sH[(row0+8)*66+col]   = fmaxf(gb*c2[mt][nt][2]+sbh1[col],   0.f);
                sH[(row0+8)*66+col+1] = fmaxf(gb*c2[mt][nt][3]+sbh1[col+1], 0.f);
            }
        }
    }
    __syncthreads();
    // ---- final 64->8 + sigmoid (2 threads/row, all 256 threads) ----
    {
        float* sH = (float*)sG0;
        int row = tid>>1, c0 = (tid&1)*4;
        int token = sSrc[row];
        if (token>=0){
            float acc0=sbh2[c0], acc1=sbh2[c0+1], acc2=sbh2[c0+2], acc3=sbh2[c0+3];
            #pragma unroll 8
            for (int k2=0;k2<64;k2++){
                float hv = sH[row*66+k2];
                acc0 += hv*sWh2[k2*8+c0];
                acc1 += hv*sWh2[k2*8+c0+1];
                acc2 += hv*sWh2[k2*8+c0+2];
                acc3 += hv*sWh2[k2*8+c0+3];
            }
            float* o = outR + (size_t)token*8 + c0;
            o[0] = 1.f/(1.f+__expf(-acc0));
            o[1] = 1.f/(1.f+__expf(-acc1));
            o[2] = 1.f/(1.f+__expf(-acc2));
            o[3] = 1.f/(1.f+__expf(-acc3));
        }
    }
}

// ---------------- launch ----------------
extern "C" void kernel_launch(void* const* d_in, const int* in_sizes, int n_in,
                              void* d_out, int out_size){
    const int *op=nullptr,*a=nullptr,*b=nullptr,*c=nullptr;
    const float *oe=nullptr,*Win=nullptr,*bin=nullptr,*Wr=nullptr,*W1=nullptr,*W2=nullptr;
    const float *Wh1=nullptr,*bh1=nullptr,*Wh2=nullptr,*bh2=nullptr;
    int nb_=0, nw=0;
    for (int i=0;i<n_in;i++){
        int s = in_sizes[i]; void* p = (void*)d_in[i];
        switch(s){
            case BTOK:
                if(nb_==0) op=(const int*)p; else if(nb_==1) a=(const int*)p;
                else if(nb_==2) b=(const int*)p; else c=(const int*)p;
                nb_++; break;
            case 256:  oe=(const float*)p; break;
            case 6272: Win=(const float*)p; break;
            case 128:  bin=(const float*)p; break;
            case 2048: Wr=(const float*)p; break;
            case 1048576: if(nw==0) W1=(const float*)p; else W2=(const float*)p; nw++; break;
            case 8192: Wh1=(const float*)p; break;
            case 64:   bh1=(const float*)p; break;
            case 512:  Wh2=(const float*)p; break;
            case 8:    bh2=(const float*)p; break;
            default: break;
        }
    }
    float* out = (float*)d_out;
    int smem = 384*SLDH*2;
    cudaFuncSetAttribute(k_ffn, cudaFuncAttributeMaxDynamicSharedMemorySize, smem);

    k_lt2<<<1,256>>>(oe,Wr,Win,bin);
    k_scalep<<<512,256>>>(W1,W2);
    k_quant<<<256,256>>>(W1,W2);
    k_u<<<128,256>>>(Win,bin);
    k_prep<<<528,256>>>(Wh1,oe);
    k_route<<<BTOK/256,256>>>(op,a,b,c,out + (size_t)BTOK*8);
    k_part<<<1,256>>>(out + (size_t)BTOK*9);
    k_ffn<<<MAXBLK,256,smem>>>(op,a,b,c,bh1,Wh2,bh2,out);
}

// round 14
// speedup vs baseline: 1.0012x; 1.0012x over previous
#include <cuda_runtime.h>
#include <cuda_fp16.h>
#include <cstdint>

#define BTOK 262144
#define DM 128
#define DFF 512
#define NT 16
#define NOPS 8
#define EMB 32
#define MROWS 128
#define SLDH 136
#define MAXBLK (BTOK/MROWS + NT)
#define TSTR (BTOK + 128)

// ---------------- device scratch ----------------
__device__ float g_Lf[NOPS*NT];
__device__ float g_Lg[256*NT];
__device__ float g_Lh[256*NT];
__device__ float g_Lc[NT];
__device__ float g_Lb[NT];
__device__ double g_sabs[32];
__device__ double g_res[2];
__device__ __half g_W1h[NT*DFF*DM];   // [t][n(dff)][k(d)]
__device__ __half g_W2h[NT*DM*DFF];   // [t][nn(d)][kk(dff)]
__device__ __half g_Wch[NT*64*DFF];   // [t][n(64)][k(dff)] = s2 * W2q @ Wh1
__device__ float  g_U[NT*50*DFF];     // [t][f(49)+bias][n(dff)]
__device__ __half g_T1g[NT*256*DFF];
__device__ __half g_T1h[NT*256*DFF];
__device__ __half g_T1fc[NT*NOPS*2*DFF];
__device__ double g_sumP[NT];
__device__ int g_fill[NT];
__device__ int g_nblocks;
__device__ float g_gate[BTOK];
__device__ int g_src[NT*TSTR];
__device__ int g_bmT[MAXBLK];
__device__ int g_bmR[MAXBLK];

// ---------------- helpers ----------------
__device__ __forceinline__ uint32_t smem_u32(const void* p){
    uint32_t a;
    asm("{ .reg .u64 t; cvta.to.shared.u64 t, %1; cvt.u32.u64 %0, t; }":"=r"(a):"l"(p));
    return a;
}
__device__ __forceinline__ void ldsm4(uint32_t* r, uint32_t addr){
    asm volatile("ldmatrix.sync.aligned.m8n8.x4.shared.b16 {%0,%1,%2,%3}, [%4];"
        : "=r"(r[0]),"=r"(r[1]),"=r"(r[2]),"=r"(r[3]) : "r"(addr));
}
__device__ __forceinline__ void mma16(float* c, const uint32_t* a, const uint32_t* b){
    asm volatile("mma.sync.aligned.m16n8k16.row.col.f32.f16.f16.f32 "
        "{%0,%1,%2,%3},{%4,%5,%6,%7},{%8,%9},{%0,%1,%2,%3};"
        : "+f"(c[0]),"+f"(c[1]),"+f"(c[2]),"+f"(c[3])
        : "r"(a[0]),"r"(a[1]),"r"(a[2]),"r"(a[3]),"r"(b[0]),"r"(b[1]));
}
__device__ __forceinline__ __half2 h2pack(float a, float b){
    return __floats2half2_rn(a, b);
}
__device__ __forceinline__ void cpa16(uint32_t dst, const void* src){
    asm volatile("cp.async.cg.shared.global [%0], [%1], 16;" :: "r"(dst),"l"(src):"memory");
}
__device__ __forceinline__ void cpa_commit(){
    asm volatile("cp.async.commit_group;":::"memory");
}
__device__ __forceinline__ void cpa_wait0(){
    asm volatile("cp.async.wait_group 0;":::"memory");
}
#define BAR_SYNC2(id)   asm volatile("bar.sync %0, 256;"   :: "r"(id) : "memory")
#define BAR_ARRIVE2(id) asm volatile("bar.arrive %0, 256;" :: "r"(id) : "memory")
#define BAR_SYNC_C()    asm volatile("bar.sync 5, 128;"    ::: "memory")

// ---------------- k_lt2: init + router logit tables (1 block) ----------------
__global__ void k_lt2(const float* __restrict__ oe, const float* __restrict__ Wr,
                      const float* __restrict__ Win, const float* __restrict__ bin){
    __shared__ float WR[50*16];
    int tid = threadIdx.x;
    if (tid < NT){ g_sumP[tid]=0.0; g_fill[tid]=0; }
    if (tid < 32) g_sabs[tid]=0.0;
    if (tid < 2)  g_res[tid]=0.0;
    for (int o = tid; o < 800; o += 256){
        int f = o>>4, tt = o&15;
        const float* src = (f<49) ? (Win + f*DM) : bin;
        float acc = 0.f;
        #pragma unroll 8
        for (int d=0; d<DM; d++) acc += src[d]*Wr[d*NT+tt];
        WR[o] = acc;
    }
    __syncthreads();
    for (int o=tid; o<NOPS*NT; o+=256){
        int opv = o>>4, tt = o&15;
        float acc = 0.f;
        #pragma unroll 8
        for (int j=0;j<EMB;j++) acc += oe[opv*EMB+j]*WR[j*16+tt];
        g_Lf[o] = acc;
    }
    for (int o=tid; o<4096; o+=256){
        int av = o>>4, tt = o&15;
        float a1=0.f, a2=0.f;
        #pragma unroll
        for (int i=0;i<8;i++) if ((av>>i)&1){ a1 += WR[(32+i)*16+tt]; a2 += WR[(40+i)*16+tt]; }
        g_Lg[o]=a1; g_Lh[o]=a2;
    }
    if (tid<16){ g_Lc[tid]=WR[48*16+tid]; g_Lb[tid]=WR[49*16+tid]; }
}

// ---------------- k_scalep ----------------
__global__ void k_scalep(const float* __restrict__ W1, const float* __restrict__ W2){
    __shared__ double red[256];
    int tile = blockIdx.x >> 4;
    int sub  = blockIdx.x & 15;
    const float* W = (tile < 16 ? W1 + tile*65536 : W2 + (tile-16)*65536) + sub*4096;
    const float4* W4 = (const float4*)W;
    double s = 0.0;
    #pragma unroll
    for (int r=0;r<4;r++){
        float4 v = W4[threadIdx.x + r*256];
        s += (double)(fabsf(v.x)+fabsf(v.y)+fabsf(v.z)+fabsf(v.w));
    }
    red[threadIdx.x]=s; __syncthreads();
    for (int o=128;o;o>>=1){ if(threadIdx.x<o) red[threadIdx.x]+=red[threadIdx.x+o]; __syncthreads(); }
    if (!threadIdx.x) atomicAdd(&g_sabs[tile], red[0]);
}

// ---------------- k_quant ----------------
__global__ void k_quant(const float* __restrict__ W1, const float* __restrict__ W2){
    __shared__ __half sh[64*130];
    __shared__ double red[256];
    int b = blockIdx.x, tid = threadIdx.x;
    double racc = 0.0;
    if (b < 128){
        int t = b>>3, n0 = (b&7)*64;
        float s = (float)(g_sabs[t]/65536.0);
        const float* src = W1 + t*65536;
        #pragma unroll
        for (int j=0;j<32;j++){
            int i = tid + j*256;
            int k = i>>6, nx = i&63;
            float w = src[k*512 + n0 + nx];
            float aw = fabsf(w);
            bool nz = aw > 0.7f*s;
            float q = nz ? (w>0.f?1.f:-1.f) : 0.f;
            racc += (double)(nz ? fabsf(aw - s) : aw);
            sh[nx*130 + k] = __float2half(q);
        }
        __syncthreads();
        __half* dst = g_W1h + t*65536 + n0*128;
        #pragma unroll
        for (int j=0;j<32;j++){
            int i = tid + j*256;
            int n = i>>7, k = i&127;
            dst[n*128 + k] = sh[n*130 + k];
        }
        red[tid]=racc; __syncthreads();
        for(int o=128;o;o>>=1){ if(tid<o) red[tid]+=red[tid+o]; __syncthreads(); }
        if (!tid) atomicAdd(&g_res[0], red[0]);
    } else {
        int bb = b-128;
        int t = bb>>3, kk0 = (bb&7)*64;
        float s = (float)(g_sabs[16+t]/65536.0);
        const float* src = W2 + t*65536;
        #pragma unroll
        for (int j=0;j<32;j++){
            int i = tid + j*256;
            int kk = i>>7, nn = i&127;
            float w = src[(kk0+kk)*128 + nn];
            float aw = fabsf(w);
            bool nz = aw > 0.7f*s;
            float q = nz ? (w>0.f?1.f:-1.f) : 0.f;
            racc += (double)(nz ? fabsf(aw - s) : aw);
            sh[kk*130 + nn] = __float2half(q);
        }
        __syncthreads();
        __half* dst = g_W2h + t*65536 + kk0;
        #pragma unroll
        for (int j=0;j<32;j++){
            int i = tid + j*256;
            int nn = i>>6, kx = i&63;
            dst[nn*512 + kx] = sh[kx*130 + nn];
        }
        red[tid]=racc; __syncthreads();
        for(int o=128;o;o>>=1){ if(tid<o) red[tid]+=red[tid+o]; __syncthreads(); }
        if (!tid) atomicAdd(&g_res[1], red[0]);
    }
}

// ---------------- k_u: U = [Win;bin] @ W1q^T per tile ----------------
__global__ void k_u(const float* __restrict__ Win, const float* __restrict__ bin){
    __shared__ float sWin[50*128];
    __shared__ __half sW[64*128];
    int b = blockIdx.x, tid = threadIdx.x;
    int t = b>>3, n0 = (b&7)*64;
    for (int i=tid; i<6400; i+=256) sWin[i] = (i<6272) ? Win[i] : bin[i-6272];
    const __half* src = g_W1h + t*65536 + n0*128;
    #pragma unroll
    for (int j=0;j<32;j++) sW[tid + j*256] = src[tid + j*256];
    __syncthreads();
    for (int o=tid; o<3200; o+=256){
        int f = o>>6, n = o&63;
        float acc = 0.f;
        #pragma unroll 8
        for (int d=0; d<128; d++)
            acc += sWin[f*128+d] * __half2float(sW[n*128+d]);
        g_U[(t*50+f)*512 + n0 + n] = acc;
    }
}

// ---------------- k_prep: merged tg(0-255) | wc(256-511) | tfc(512-527) ----------------
__global__ void k_prep(const float* __restrict__ Wh1, const float* __restrict__ oe){
    __shared__ char buf[41984];
    int b = blockIdx.x, tid = threadIdx.x;
    if (b < 256){
        float* sU = (float*)buf;                 // 8*512 floats = 16KB
        int t = b>>4, which = (b>>3)&1, av0 = (b&7)*32;
        for (int i=tid; i<4096; i+=256)
            sU[i] = g_U[(t*50 + 32 + which*8 + (i>>9))*512 + (i&511)];
        float s1 = (float)(g_sabs[t]/65536.0);
        __half* dst = (which ? g_T1h : g_T1g) + ((size_t)t<<17) + (size_t)av0*512;
        __syncthreads();
        for (int o=tid; o<16384; o+=256){
            int av = av0 + (o>>9), n = o&511;
            float acc = 0.f;
            #pragma unroll
            for (int i=0;i<8;i++) if ((av>>i)&1) acc += sU[i*512+n];
            dst[o] = __float2half(s1*acc);
        }
    } else if (b < 512){
        float* sWh1 = (float*)buf;               // 128*64 floats = 32KB
        __half* sW2 = (__half*)(buf + 32768);    // 128*32 halves = 8KB
        int bb = b-256;
        int t = bb>>4, k0 = (bb&15)*32;
        float s2 = (float)(g_sabs[16+t]/65536.0);
        #pragma unroll
        for (int j=0;j<32;j++) sWh1[tid + j*256] = Wh1[tid + j*256];
        const __half* W2p = g_W2h + t*65536 + k0;
        #pragma unroll
        for (int j=0;j<16;j++){
            int i = tid + j*256;
            int d = i>>5, kx = i&31;
            sW2[d*32 + kx] = W2p[d*512 + kx];
        }
        __syncthreads();
        #pragma unroll
        for (int j=0;j<8;j++){
            int o = tid + j*256;
            int n = o&63, kx = o>>6;
            float acc = 0.f;
            #pragma unroll 8
            for (int d=0; d<128; d++)
                acc += __half2float(sW2[d*32 + kx]) * sWh1[d*64 + n];
            g_Wch[t*32768 + n*512 + k0 + kx] = __float2half(s2*acc);
        }
    } else {
        int t = b-512;
        float s1 = (float)(g_sabs[t]/65536.0);
        for (int o=tid; o<8192; o+=256){
            int n = o&511, cc = (o>>9)&1, opv = o>>10;
            float acc = g_U[(t*50+49)*512+n];
            if (cc) acc += g_U[(t*50+48)*512+n];
            #pragma unroll 8
            for (int j=0;j<32;j++)
                acc += oe[opv*32+j] * g_U[(t*50+j)*512+n];
            g_T1fc[t*8192 + o] = __float2half(s1*acc);
        }
    }
}

// ---------------- k_route ----------------
__global__ void k_route(const int* __restrict__ op, const int* __restrict__ a,
                        const int* __restrict__ b, const int* __restrict__ c,
                        float* __restrict__ outIdx){
    __shared__ float sLf[NOPS*NT], sLg[256*NT], sLh[256*NT], sLc[NT], sLb[NT];
    __shared__ float sP[NT]; __shared__ int sC[NT]; __shared__ int sBase[NT];
    int tid = threadIdx.x;
    int lane = tid & 31;
    for (int i=tid;i<256*NT;i+=256){ sLg[i]=g_Lg[i]; sLh[i]=g_Lh[i]; }
    for (int i=tid;i<NOPS*NT;i+=256) sLf[i]=g_Lf[i];
    if (tid<NT){ sLc[tid]=g_Lc[tid]; sLb[tid]=g_Lb[tid]; sP[tid]=0.f; sC[tid]=0; }
    __syncthreads();
    int i = blockIdx.x*256+tid;
    int opv=op[i], av=a[i], bv=b[i]; float cv=(float)c[i];
    float l[NT]; float mx=-1e30f; int best=0;
    #pragma unroll
    for (int t=0;t<NT;t++){
        float v = sLf[opv*NT+t]+sLg[av*NT+t]+sLh[bv*NT+t]+cv*sLc[t]+sLb[t];
        l[t]=v;
        if (v>mx){mx=v;best=t;}
    }
    float den=0.f;
    #pragma unroll
    for (int t=0;t<NT;t++){ l[t]=__expf(l[t]-mx); den+=l[t]; }
    float inv = 1.f/den;
    #pragma unroll
    for (int t=0;t<NT;t++){
        float v = l[t]*inv;
        #pragma unroll
        for (int o=16;o;o>>=1) v += __shfl_xor_sync(0xffffffffu, v, o);
        if (lane==0) atomicAdd(&sP[t], v);
    }
    int rank = atomicAdd(&sC[best], 1);
    g_gate[i]=inv; outIdx[i]=(float)best;
    __syncthreads();
    if (tid<NT){
        sBase[tid] = atomicAdd(&g_fill[tid], sC[tid]);
        atomicAdd(&g_sumP[tid], (double)sP[tid]);
    }
    __syncthreads();
    g_src[best*TSTR + sBase[best] + rank] = i;
}

// ---------------- k_part (+ fused aux) ----------------
__global__ void k_part(float* __restrict__ aux){
    __shared__ int pc[NT], po_[NT];
    int tid=threadIdx.x;
    if (tid<NT) pc[tid] = g_fill[tid];
    __syncthreads();
    if (tid==0){
        int nb=0;
        for (int t=0;t<NT;t++){ po_[t]=nb; nb += (pc[t]+MROWS-1)/MROWS; }
        g_nblocks = nb;
    }
    if (tid==32){
        double sp=0.0, cp[4]={0,0,0,0};
        for (int t=0;t<NT;t++){
            double frac = (double)g_fill[t]/(double)BTOK;
            double mp = g_sumP[t]/(double)BTOK;
            sp += frac*mp;
            cp[t>>2] += mp;
        }
        double sparsity = 16.0*sp;
        double tern = g_res[0]/1048576.0 + g_res[1]/1048576.0;
        double divv = 0.0;
        for (int i=0;i<4;i++) divv += cp[i]*log(cp[i]+1e-9);
        aux[0] = (float)(0.01*tern + 0.005*sparsity + 0.01*divv);
    }
    __syncthreads();
    for (int t=0;t<NT;t++){
        int bl = (pc[t]+MROWS-1)/MROWS;
        for (int bi=tid; bi<bl; bi+=256){ g_bmT[po_[t]+bi]=t; g_bmR[po_[t]+bi]=t*TSTR + bi*MROWS; }
        int cnt=pc[t]; int pad = bl*MROWS;
        for (int p=cnt+tid; p<pad; p+=256) g_src[t*TSTR+p] = -1;
    }
}

// ---------------- k_ffn: warp-specialized producer/consumer ----------------
__global__ void __launch_bounds__(256,2) k_ffn(
    const int* __restrict__ op, const int* __restrict__ aIn,
    const int* __restrict__ bIn, const int* __restrict__ cIn,
    const float* __restrict__ bh1,
    const float* __restrict__ Wh2, const float* __restrict__ bh2,
    float* __restrict__ outR)
{
    extern __shared__ __half sm[];
    __half* sG0 = sm;                       // [128][SLDH]
    __half* sG1 = sm + 128*SLDH;            // [128][SLDH]
    __half* sW0 = sm + 256*SLDH;            // [64][SLDH]
    __half* sW1 = sW0 + 64*SLDH;            // [64][SLDH]
    __shared__ float sGate[MROWS];
    __shared__ int   sSrc[MROWS];
    __shared__ int   sAV[MROWS], sBV[MROWS], sOC[MROWS];
    __shared__ float sWh2[512], sbh1[64], sbh2[8];

    int bid = blockIdx.x;
    if (bid >= g_nblocks) return;
    int t  = g_bmT[bid], r0 = g_bmR[bid];
    int tid = threadIdx.x;
    int wid = tid>>5, lane = tid&31;

    if (tid < 128){
        int token = g_src[r0+tid];
        sSrc[tid] = token;
        if (token>=0){
            sGate[tid] = g_gate[token];
            sAV[tid] = aIn[token];
            sBV[tid] = bIn[token];
            sOC[tid] = (t*8 + op[token])*2 + cIn[token];
        } else {
            sGate[tid]=0.f; sAV[tid]=0; sBV[tid]=0; sOC[tid]=t*16;
        }
    }
    for (int i=tid;i<512;i+=256) sWh2[i]=Wh2[i];
    if (tid<64) sbh1[tid]=bh1[tid];
    if (tid<8)  sbh2[tid]=bh2[tid];
    __syncthreads();

    uint32_t gbuf[2] = { smem_u32(sG0), smem_u32(sG1) };
    uint32_t wbuf[2] = { smem_u32(sW0), smem_u32(sW1) };

    if (wid < 4){
        // ================= PRODUCER =================
        int lt4 = lane>>3, lc8 = lane&7;
        const __half2 C0 = __floats2half2_rn(0.044715f, 0.044715f);
        const __half2 C1 = __floats2half2_rn(0.7978845608f, 0.7978845608f);
        const __half2 ONE = __floats2half2_rn(1.f, 1.f);
        const __half2 HLF = __floats2half2_rn(0.5f, 0.5f);
        for (int ch=0; ch<4; ch++){
            int buf = ch&1;
            if (ch>=2) BAR_SYNC2(3+buf);
            __half* gdst = buf ? sG1 : sG0;
            #pragma unroll
            for (int it=0; it<8; it++){
                int row = wid*32 + it*4 + lt4;
                int token = sSrc[row];
                __half* dst = gdst + row*SLDH + lc8*8;
                if (token>=0){
                    const __half* pg = g_T1g + ((((size_t)(t<<8)+sAV[row])<<9) + ch*128 + lc8*8);
                    const __half* ph = g_T1h + ((((size_t)(t<<8)+sBV[row])<<9) + ch*128 + lc8*8);
                    const __half* pf = g_T1fc + (((size_t)sOC[row]<<9) + ch*128 + lc8*8);
                    #pragma unroll
                    for (int seg=0; seg<2; seg++){
                        int off = seg*64;
                        uint4 va = *(const uint4*)(pg+off);
                        uint4 vb = *(const uint4*)(ph+off);
                        uint4 vf = *(const uint4*)(pf+off);
                        __half2* ha=(__half2*)&va;
                        __half2* hb=(__half2*)&vb;
                        __half2* hf=(__half2*)&vf;
                        uint4 ou; __half2* ho=(__half2*)&ou;
                        #pragma unroll
                        for (int q=0;q<4;q++){
                            __half2 v  = __hadd2(__hadd2(ha[q],hb[q]), hf[q]);
                            __half2 v2 = __hmul2(v,v);
                            __half2 v3 = __hmul2(v2,v);
                            __half2 in2= __hfma2(v3, C0, v);
                            __half2 u  = __hmul2(in2, C1);
                            uint32_t ur = *(uint32_t*)&u, tr;
                            asm("tanh.approx.f16x2 %0, %1;" : "=r"(tr) : "r"(ur));
                            __half2 th = *(__half2*)&tr;
                            __half2 onep = __hadd2(th, ONE);
                            __half2 hv = __hmul2(v, HLF);
                            ho[q] = __hmul2(hv, onep);
                        }
                        *(uint4*)(dst+off) = ou;
                    }
                } else {
                    uint4 z = make_uint4(0,0,0,0);
                    *(uint4*)(dst) = z;
                    *(uint4*)(dst+64) = z;
                }
            }
            BAR_ARRIVE2(1+buf);
        }
    } else {
        // ================= CONSUMER =================
        int cm = wid-4;
        int ctid = cm*32 + lane;
        int grp = lane>>2, tq = lane&3;
        uint32_t aoff  = (uint32_t)((lane&15)*SLDH + (lane>>4)*8)*2;
        uint32_t boff4 = (uint32_t)(((lane&7) + ((lane>>4)<<3))*SLDH + ((lane>>3)&1)*8)*2;
        const __half* Wcp = g_Wch + t*32768;

        #pragma unroll
        for (int j=0;j<8;j++){
            int i = ctid + j*128;
            int row = i>>4, ck = i&15;
            cpa16(wbuf[0] + (uint32_t)(row*SLDH + ck*8)*2, Wcp + row*512 + ck*8);
        }
        cpa_commit();

        float c2[2][8][4];
        #pragma unroll
        for(int mt=0;mt<2;mt++)
            #pragma unroll
            for(int nt=0;nt<8;nt++)
                #pragma unroll
                for(int e=0;e<4;e++) c2[mt][nt][e]=0.f;

        for (int ch=0; ch<4; ch++){
            int buf = ch&1;
            cpa_wait0();
            BAR_SYNC_C();
            BAR_SYNC2(1+buf);
            if (ch<3){
                const __half* src = Wcp + (ch+1)*128;
                #pragma unroll
                for (int j=0;j<8;j++){
                    int i = ctid + j*128;
                    int row = i>>4, ck = i&15;
                    cpa16(wbuf[(ch+1)&1] + (uint32_t)(row*SLDH + ck*8)*2, src + row*512 + ck*8);
                }
                cpa_commit();
            }
            uint32_t bg = gbuf[buf], bw = wbuf[buf];
            #pragma unroll
            for (int kk=0;kk<8;kk++){
                uint32_t af[2][4];
                ldsm4(af[0], bg + aoff + (uint32_t)((cm*32)*SLDH + kk*16)*2);
                ldsm4(af[1], bg + aoff + (uint32_t)((cm*32+16)*SLDH + kk*16)*2);
                #pragma unroll
                for (int ntp=0;ntp<4;ntp++){
                    uint32_t bq[4];
                    ldsm4(bq, bw + boff4 + (uint32_t)((ntp*16)*SLDH + kk*16)*2);
                    mma16(c2[0][2*ntp],   af[0], bq);
                    mma16(c2[1][2*ntp],   af[1], bq);
                    mma16(c2[0][2*ntp+1], af[0], bq+2);
                    mma16(c2[1][2*ntp+1], af[1], bq+2);
                }
            }
            if (ch<2) BAR_ARRIVE2(3+buf);
        }

        // ---- epilogue: h = relu(gate*c2 + bh1) -> sH (overwrites sG0) ----
        float* sH = (float*)sG0;   // [128][66]
        #pragma unroll
        for (int mt=0;mt<2;mt++){
            int row0 = cm*32+mt*16+grp;
            float ga = sGate[row0], gb = sGate[row0+8];
            #pragma unroll
            for (int nt=0;nt<8;nt++){
                int col = nt*8+2*tq;
                sH[row0*66+col]       = fmaxf(ga*c2[mt][nt][0]+sbh1[col],   0.f);
                sH[row0*66+col+1]     = fmaxf(ga*c2[mt][nt][1]+sbh1[col+1], 0.f);
                sH[(row0+8)*66+col]   = fmaxf(gb*c2[mt][nt][2]+sbh1[col],   0.f);
                sH[(row0+8)*66+col+1] = fmaxf(gb*c2[mt][nt][3]+sbh1[col+1], 0.f);
            }
        }
    }
    __syncthreads();
    // ---- final 64->8 + sigmoid (2 threads/row, all 256 threads) ----
    {
        float* sH = (float*)sG0;
        int row = tid>>1, c0 = (tid&1)*4;
        int token = sSrc[row];
        if (token>=0){
            float acc0=sbh2[c0], acc1=sbh2[c0+1], acc2=sbh2[c0+2], acc3=sbh2[c0+3];
            #pragma unroll 8
            for (int k2=0;k2<64;k2++){
                float hv = sH[row*66+k2];
                acc0 += hv*sWh2[k2*8+c0];
                acc1 += hv*sWh2[k2*8+c0+1];
                acc2 += hv*sWh2[k2*8+c0+2];
                acc3 += hv*sWh2[k2*8+c0+3];
            }
            float* o = outR + (size_t)token*8 + c0;
            o[0] = 1.f/(1.f+__expf(-acc0));
            o[1] = 1.f/(1.f+__expf(-acc1));
            o[2] = 1.f/(1.f+__expf(-acc2));
            o[3] = 1.f/(1.f+__expf(-acc3));
        }
    }
}

// ---------------- launch ----------------
extern "C" void kernel_launch(void* const* d_in, const int* in_sizes, int n_in,
                              void* d_out, int out_size){
    const int *op=nullptr,*a=nullptr,*b=nullptr,*c=nullptr;
    const float *oe=nullptr,*Win=nullptr,*bin=nullptr,*Wr=nullptr,*W1=nullptr,*W2=nullptr;
    const float *Wh1=nullptr,*bh1=nullptr,*Wh2=nullptr,*bh2=nullptr;
    int nb_=0, nw=0;
    for (int i=0;i<n_in;i++){
        int s = in_sizes[i]; void* p = (void*)d_in[i];
        switch(s){
            case BTOK:
                if(nb_==0) op=(const int*)p; else if(nb_==1) a=(const int*)p;
                else if(nb_==2) b=(const int*)p; else c=(const int*)p;
                nb_++; break;
            case 256:  oe=(const float*)p; break;
            case 6272: Win=(const float*)p; break;
            case 128:  bin=(const float*)p; break;
            case 2048: Wr=(const float*)p; break;
            case 1048576: if(nw==0) W1=(const float*)p; else W2=(const float*)p; nw++; break;
            case 8192: Wh1=(const float*)p; break;
            case 64:   bh1=(const float*)p; break;
            case 512:  Wh2=(const float*)p; break;
            case 8:    bh2=(const float*)p; break;
            default: break;
        }
    }
    float* out = (float*)d_out;
    int smem = 384*SLDH*2;
    cudaFuncSetAttribute(k_ffn, cudaFuncAttributeMaxDynamicSharedMemorySize, smem);

    k_lt2<<<1,256>>>(oe,Wr,Win,bin);
    k_scalep<<<512,256>>>(W1,W2);
    k_quant<<<256,256>>>(W1,W2);
    k_u<<<128,256>>>(Win,bin);
    k_prep<<<528,256>>>(Wh1,oe);
    k_route<<<BTOK/256,256>>>(op,a,b,c,out + (size_t)BTOK*8);
    k_part<<<1,256>>>(out + (size_t)BTOK*9);
    k_ffn<<<MAXBLK,256,smem>>>(op,a,b,c,bh1,Wh2,bh2,out);
}

// round 15
// speedup vs baseline: 1.1281x; 1.1268x over previous
#include <cuda_runtime.h>
#include <cuda_fp16.h>
#include <cstdint>

#define BTOK 262144
#define DM 128
#define DFF 512
#define NT 16
#define NOPS 8
#define EMB 32
#define MROWS 128
#define SLDH 136
#define MAXBLK (BTOK/MROWS + NT)
#define TSTR (BTOK + 128)

// ---------------- device scratch ----------------
__device__ float g_Lf[NOPS*NT];
__device__ float g_Lg[256*NT];
__device__ float g_Lh[256*NT];
__device__ float g_Lc[NT];
__device__ float g_Lb[NT];
__device__ double g_sabs[32];
__device__ double g_res[2];
__device__ __half g_W1h[NT*DFF*DM];   // [t][n(dff)][k(d)]
__device__ __half g_W2h[NT*DM*DFF];   // [t][nn(d)][kk(dff)]
__device__ __half g_Wch[NT*64*DFF];   // [t][n(64)][k(dff)] = s2 * W2q @ Wh1
__device__ float  g_U[NT*50*DFF];     // [t][f(49)+bias][n(dff)]
__device__ __half g_T1g[NT*256*DFF];
__device__ __half g_T1h[NT*256*DFF];
__device__ __half g_T1fc[NT*NOPS*2*DFF];
__device__ double g_sumP[NT];
__device__ int g_fill[NT];
__device__ int g_nblocks;
__device__ float g_gate[BTOK];
__device__ int g_src[NT*TSTR];
__device__ int g_bmT[MAXBLK];
__device__ int g_bmR[MAXBLK];

// ---------------- helpers ----------------
__device__ __forceinline__ uint32_t smem_u32(const void* p){
    uint32_t a;
    asm("{ .reg .u64 t; cvta.to.shared.u64 t, %1; cvt.u32.u64 %0, t; }":"=r"(a):"l"(p));
    return a;
}
__device__ __forceinline__ void ldsm4(uint32_t* r, uint32_t addr){
    asm volatile("ldmatrix.sync.aligned.m8n8.x4.shared.b16 {%0,%1,%2,%3}, [%4];"
        : "=r"(r[0]),"=r"(r[1]),"=r"(r[2]),"=r"(r[3]) : "r"(addr));
}
__device__ __forceinline__ void mma16(float* c, const uint32_t* a, const uint32_t* b){
    asm volatile("mma.sync.aligned.m16n8k16.row.col.f32.f16.f16.f32 "
        "{%0,%1,%2,%3},{%4,%5,%6,%7},{%8,%9},{%0,%1,%2,%3};"
        : "+f"(c[0]),"+f"(c[1]),"+f"(c[2]),"+f"(c[3])
        : "r"(a[0]),"r"(a[1]),"r"(a[2]),"r"(a[3]),"r"(b[0]),"r"(b[1]));
}
__device__ __forceinline__ __half2 h2pack(float a, float b){
    return __floats2half2_rn(a, b);
}
__device__ __forceinline__ void cpa16(uint32_t dst, const void* src){
    asm volatile("cp.async.cg.shared.global [%0], [%1], 16;" :: "r"(dst),"l"(src):"memory");
}
__device__ __forceinline__ void cpa_commit(){
    asm volatile("cp.async.commit_group;":::"memory");
}
__device__ __forceinline__ void cpa_wait0(){
    asm volatile("cp.async.wait_group 0;":::"memory");
}
#define BAR_SYNC2(id)   asm volatile("bar.sync %0, 256;"   :: "r"(id) : "memory")
#define BAR_ARRIVE2(id) asm volatile("bar.arrive %0, 256;" :: "r"(id) : "memory")
#define BAR_SYNC_C()    asm volatile("bar.sync 5, 128;"    ::: "memory")

// ---------------- k_lt2: init + router logit tables (1 block) ----------------
__global__ void k_lt2(const float* __restrict__ oe, const float* __restrict__ Wr,
                      const float* __restrict__ Win, const float* __restrict__ bin){
    __shared__ float WR[50*16];
    int tid = threadIdx.x;
    if (tid < NT){ g_sumP[tid]=0.0; g_fill[tid]=0; }
    if (tid < 32) g_sabs[tid]=0.0;
    if (tid < 2)  g_res[tid]=0.0;
    for (int o = tid; o < 800; o += 256){
        int f = o>>4, tt = o&15;
        const float* src = (f<49) ? (Win + f*DM) : bin;
        float acc = 0.f;
        #pragma unroll 8
        for (int d=0; d<DM; d++) acc += src[d]*Wr[d*NT+tt];
        WR[o] = acc;
    }
    __syncthreads();
    for (int o=tid; o<NOPS*NT; o+=256){
        int opv = o>>4, tt = o&15;
        float acc = 0.f;
        #pragma unroll 8
        for (int j=0;j<EMB;j++) acc += oe[opv*EMB+j]*WR[j*16+tt];
        g_Lf[o] = acc;
    }
    for (int o=tid; o<4096; o+=256){
        int av = o>>4, tt = o&15;
        float a1=0.f, a2=0.f;
        #pragma unroll
        for (int i=0;i<8;i++) if ((av>>i)&1){ a1 += WR[(32+i)*16+tt]; a2 += WR[(40+i)*16+tt]; }
        g_Lg[o]=a1; g_Lh[o]=a2;
    }
    if (tid<16){ g_Lc[tid]=WR[48*16+tid]; g_Lb[tid]=WR[49*16+tid]; }
}

// ---------------- k_scalep: 4 independent accumulators ----------------
__global__ void k_scalep(const float* __restrict__ W1, const float* __restrict__ W2){
    __shared__ double red[256];
    int tile = blockIdx.x >> 4;
    int sub  = blockIdx.x & 15;
    const float* W = (tile < 16 ? W1 + tile*65536 : W2 + (tile-16)*65536) + sub*4096;
    const float4* W4 = (const float4*)W;
    double s0=0.0,s1=0.0,s2=0.0,s3=0.0;
    float4 v0 = W4[threadIdx.x];
    float4 v1 = W4[threadIdx.x + 256];
    float4 v2 = W4[threadIdx.x + 512];
    float4 v3 = W4[threadIdx.x + 768];
    s0 += (double)(fabsf(v0.x)+fabsf(v0.y)+fabsf(v0.z)+fabsf(v0.w));
    s1 += (double)(fabsf(v1.x)+fabsf(v1.y)+fabsf(v1.z)+fabsf(v1.w));
    s2 += (double)(fabsf(v2.x)+fabsf(v2.y)+fabsf(v2.z)+fabsf(v2.w));
    s3 += (double)(fabsf(v3.x)+fabsf(v3.y)+fabsf(v3.z)+fabsf(v3.w));
    red[threadIdx.x]=(s0+s1)+(s2+s3); __syncthreads();
    for (int o=128;o;o>>=1){ if(threadIdx.x<o) red[threadIdx.x]+=red[threadIdx.x+o]; __syncthreads(); }
    if (!threadIdx.x) atomicAdd(&g_sabs[tile], red[0]);
}

// ---------------- k_quant ----------------
__global__ void k_quant(const float* __restrict__ W1, const float* __restrict__ W2){
    __shared__ __half sh[64*130];
    __shared__ double red[256];
    int b = blockIdx.x, tid = threadIdx.x;
    double racc = 0.0;
    if (b < 128){
        int t = b>>3, n0 = (b&7)*64;
        float s = (float)(g_sabs[t]/65536.0);
        const float* src = W1 + t*65536;
        #pragma unroll
        for (int j=0;j<32;j++){
            int i = tid + j*256;
            int k = i>>6, nx = i&63;
            float w = src[k*512 + n0 + nx];
            float aw = fabsf(w);
            bool nz = aw > 0.7f*s;
            float q = nz ? (w>0.f?1.f:-1.f) : 0.f;
            racc += (double)(nz ? fabsf(aw - s) : aw);
            sh[nx*130 + k] = __float2half(q);
        }
        __syncthreads();
        __half* dst = g_W1h + t*65536 + n0*128;
        #pragma unroll
        for (int j=0;j<32;j++){
            int i = tid + j*256;
            int n = i>>7, k = i&127;
            dst[n*128 + k] = sh[n*130 + k];
        }
        red[tid]=racc; __syncthreads();
        for(int o=128;o;o>>=1){ if(tid<o) red[tid]+=red[tid+o]; __syncthreads(); }
        if (!tid) atomicAdd(&g_res[0], red[0]);
    } else {
        int bb = b-128;
        int t = bb>>3, kk0 = (bb&7)*64;
        float s = (float)(g_sabs[16+t]/65536.0);
        const float* src = W2 + t*65536;
        #pragma unroll
        for (int j=0;j<32;j++){
            int i = tid + j*256;
            int kk = i>>7, nn = i&127;
            float w = src[(kk0+kk)*128 + nn];
            float aw = fabsf(w);
            bool nz = aw > 0.7f*s;
            float q = nz ? (w>0.f?1.f:-1.f) : 0.f;
            racc += (double)(nz ? fabsf(aw - s) : aw);
            sh[kk*130 + nn] = __float2half(q);
        }
        __syncthreads();
        __half* dst = g_W2h + t*65536 + kk0;
        #pragma unroll
        for (int j=0;j<32;j++){
            int i = tid + j*256;
            int nn = i>>6, kx = i&63;
            dst[nn*512 + kx] = sh[kx*130 + nn];
        }
        red[tid]=racc; __syncthreads();
        for(int o=128;o;o>>=1){ if(tid<o) red[tid]+=red[tid+o]; __syncthreads(); }
        if (!tid) atomicAdd(&g_res[1], red[0]);
    }
}

// ---------------- k_u: U = [Win;bin] @ W1q^T, conflict-free layout ----------------
// grid 256: t = b>>4, n0 = (b&15)*32
__global__ void k_u(const float* __restrict__ Win, const float* __restrict__ bin){
    __shared__ float sWin[50*128];     // 25.6KB
    __shared__ float sWd[128*32];      // [d][n] 16KB, read bank = n (conflict-free)
    int b = blockIdx.x, tid = threadIdx.x;
    int t = b>>4, n0 = (b&15)*32;
    for (int i=tid; i<6400; i+=256) sWin[i] = (i<6272) ? Win[i] : bin[i-6272];
    const __half* src = g_W1h + t*65536 + n0*128;
    for (int i=tid; i<4096; i+=256){
        int n = i>>7, d = i&127;
        sWd[d*32+n] = __half2float(src[i]);
    }
    __syncthreads();
    for (int o=tid; o<1600; o+=256){
        int f = o>>5, n = o&31;
        const float* wf = sWin + f*128;
        float acc = 0.f;
        #pragma unroll 16
        for (int d=0; d<128; d++)
            acc += wf[d]*sWd[d*32+n];
        g_U[(t*50+f)*512 + n0 + n] = acc;
    }
}

// ---------------- k_prep: merged tg(0-255) | wc(256-511) | tfc(512-527) ----------------
__global__ void k_prep(const float* __restrict__ Wh1, const float* __restrict__ oe){
    __shared__ char buf[41984];
    int b = blockIdx.x, tid = threadIdx.x;
    if (b < 256){
        float* sU = (float*)buf;
        int t = b>>4, which = (b>>3)&1, av0 = (b&7)*32;
        for (int i=tid; i<4096; i+=256)
            sU[i] = g_U[(t*50 + 32 + which*8 + (i>>9))*512 + (i&511)];
        float s1 = (float)(g_sabs[t]/65536.0);
        __half* dst = (which ? g_T1h : g_T1g) + ((size_t)t<<17) + (size_t)av0*512;
        __syncthreads();
        for (int o=tid; o<16384; o+=256){
            int av = av0 + (o>>9), n = o&511;
            float acc = 0.f;
            #pragma unroll
            for (int i=0;i<8;i++) if ((av>>i)&1) acc += sU[i*512+n];
            dst[o] = __float2half(s1*acc);
        }
    } else if (b < 512){
        float* sWh1 = (float*)buf;
        __half* sW2 = (__half*)(buf + 32768);
        int bb = b-256;
        int t = bb>>4, k0 = (bb&15)*32;
        float s2 = (float)(g_sabs[16+t]/65536.0);
        #pragma unroll
        for (int j=0;j<32;j++) sWh1[tid + j*256] = Wh1[tid + j*256];
        const __half* W2p = g_W2h + t*65536 + k0;
        #pragma unroll
        for (int j=0;j<16;j++){
            int i = tid + j*256;
            int d = i>>5, kx = i&31;
            sW2[d*32 + kx] = W2p[d*512 + kx];
        }
        __syncthreads();
        #pragma unroll
        for (int j=0;j<8;j++){
            int o = tid + j*256;
            int n = o&63, kx = o>>6;
            float acc = 0.f;
            #pragma unroll 8
            for (int d=0; d<128; d++)
                acc += __half2float(sW2[d*32 + kx]) * sWh1[d*64 + n];
            g_Wch[t*32768 + n*512 + k0 + kx] = __float2half(s2*acc);
        }
    } else {
        int t = b-512;
        float s1 = (float)(g_sabs[t]/65536.0);
        for (int o=tid; o<8192; o+=256){
            int n = o&511, cc = (o>>9)&1, opv = o>>10;
            float acc = g_U[(t*50+49)*512+n];
            if (cc) acc += g_U[(t*50+48)*512+n];
            #pragma unroll 8
            for (int j=0;j<32;j++)
                acc += oe[opv*32+j] * g_U[(t*50+j)*512+n];
            g_T1fc[t*8192 + o] = __float2half(s1*acc);
        }
    }
}

// ---------------- k_route ----------------
__global__ void k_route(const int* __restrict__ op, const int* __restrict__ a,
                        const int* __restrict__ b, const int* __restrict__ c,
                        float* __restrict__ outIdx){
    __shared__ float sLf[NOPS*NT], sLg[256*NT], sLh[256*NT], sLc[NT], sLb[NT];
    __shared__ float sP[NT]; __shared__ int sC[NT]; __shared__ int sBase[NT];
    int tid = threadIdx.x;
    int lane = tid & 31;
    for (int i=tid;i<256*NT;i+=256){ sLg[i]=g_Lg[i]; sLh[i]=g_Lh[i]; }
    for (int i=tid;i<NOPS*NT;i+=256) sLf[i]=g_Lf[i];
    if (tid<NT){ sLc[tid]=g_Lc[tid]; sLb[tid]=g_Lb[tid]; sP[tid]=0.f; sC[tid]=0; }
    __syncthreads();
    int i = blockIdx.x*256+tid;
    int opv=op[i], av=a[i], bv=b[i]; float cv=(float)c[i];
    float l[NT]; float mx=-1e30f; int best=0;
    #pragma unroll
    for (int t=0;t<NT;t++){
        float v = sLf[opv*NT+t]+sLg[av*NT+t]+sLh[bv*NT+t]+cv*sLc[t]+sLb[t];
        l[t]=v;
        if (v>mx){mx=v;best=t;}
    }
    float den=0.f;
    #pragma unroll
    for (int t=0;t<NT;t++){ l[t]=__expf(l[t]-mx); den+=l[t]; }
    float inv = 1.f/den;
    #pragma unroll
    for (int t=0;t<NT;t++){
        float v = l[t]*inv;
        #pragma unroll
        for (int o=16;o;o>>=1) v += __shfl_xor_sync(0xffffffffu, v, o);
        if (lane==0) atomicAdd(&sP[t], v);
    }
    int rank = atomicAdd(&sC[best], 1);
    g_gate[i]=inv; outIdx[i]=(float)best;
    __syncthreads();
    if (tid<NT){
        sBase[tid] = atomicAdd(&g_fill[tid], sC[tid]);
        atomicAdd(&g_sumP[tid], (double)sP[tid]);
    }
    __syncthreads();
    g_src[best*TSTR + sBase[best] + rank] = i;
}

// ---------------- k_part (+ fused aux) ----------------
__global__ void k_part(float* __restrict__ aux){
    __shared__ int pc[NT], po_[NT];
    int tid=threadIdx.x;
    if (tid<NT) pc[tid] = g_fill[tid];
    __syncthreads();
    if (tid==0){
        int nb=0;
        for (int t=0;t<NT;t++){ po_[t]=nb; nb += (pc[t]+MROWS-1)/MROWS; }
        g_nblocks = nb;
    }
    if (tid==32){
        double sp=0.0, cp[4]={0,0,0,0};
        for (int t=0;t<NT;t++){
            double frac = (double)g_fill[t]/(double)BTOK;
            double mp = g_sumP[t]/(double)BTOK;
            sp += frac*mp;
            cp[t>>2] += mp;
        }
        double sparsity = 16.0*sp;
        double tern = g_res[0]/1048576.0 + g_res[1]/1048576.0;
        double divv = 0.0;
        for (int i=0;i<4;i++) divv += cp[i]*log(cp[i]+1e-9);
        aux[0] = (float)(0.01*tern + 0.005*sparsity + 0.01*divv);
    }
    __syncthreads();
    for (int t=0;t<NT;t++){
        int bl = (pc[t]+MROWS-1)/MROWS;
        for (int bi=tid; bi<bl; bi+=256){ g_bmT[po_[t]+bi]=t; g_bmR[po_[t]+bi]=t*TSTR + bi*MROWS; }
        int cnt=pc[t]; int pad = bl*MROWS;
        for (int p=cnt+tid; p<pad; p+=256) g_src[t*TSTR+p] = -1;
    }
}

// ---------------- k_ffn: warp-specialized producer/consumer ----------------
__global__ void __launch_bounds__(256,2) k_ffn(
    const int* __restrict__ op, const int* __restrict__ aIn,
    const int* __restrict__ bIn, const int* __restrict__ cIn,
    const float* __restrict__ bh1,
    const float* __restrict__ Wh2, const float* __restrict__ bh2,
    float* __restrict__ outR)
{
    extern __shared__ __half sm[];
    __half* sG0 = sm;
    __half* sG1 = sm + 128*SLDH;
    __half* sW0 = sm + 256*SLDH;
    __half* sW1 = sW0 + 64*SLDH;
    __shared__ float sGate[MROWS];
    __shared__ int   sSrc[MROWS];
    __shared__ int   sAV[MROWS], sBV[MROWS], sOC[MROWS];
    __shared__ float sWh2[512], sbh1[64], sbh2[8];

    int bid = blockIdx.x;
    if (bid >= g_nblocks) return;
    int t  = g_bmT[bid], r0 = g_bmR[bid];
    int tid = threadIdx.x;
    int wid = tid>>5, lane = tid&31;

    if (tid < 128){
        int token = g_src[r0+tid];
        sSrc[tid] = token;
        if (token>=0){
            sGate[tid] = g_gate[token];
            sAV[tid] = aIn[token];
            sBV[tid] = bIn[token];
            sOC[tid] = (t*8 + op[token])*2 + cIn[token];
        } else {
            sGate[tid]=0.f; sAV[tid]=0; sBV[tid]=0; sOC[tid]=t*16;
        }
    }
    for (int i=tid;i<512;i+=256) sWh2[i]=Wh2[i];
    if (tid<64) sbh1[tid]=bh1[tid];
    if (tid<8)  sbh2[tid]=bh2[tid];
    __syncthreads();

    uint32_t gbuf[2] = { smem_u32(sG0), smem_u32(sG1) };
    uint32_t wbuf[2] = { smem_u32(sW0), smem_u32(sW1) };

    if (wid < 4){
        // ================= PRODUCER =================
        int lt4 = lane>>3, lc8 = lane&7;
        const __half2 C0 = __floats2half2_rn(0.044715f, 0.044715f);
        const __half2 C1 = __floats2half2_rn(0.7978845608f, 0.7978845608f);
        const __half2 ONE = __floats2half2_rn(1.f, 1.f);
        const __half2 HLF = __floats2half2_rn(0.5f, 0.5f);
        for (int ch=0; ch<4; ch++){
            int buf = ch&1;
            if (ch>=2) BAR_SYNC2(3+buf);
            __half* gdst = buf ? sG1 : sG0;
            #pragma unroll
            for (int it=0; it<8; it++){
                int row = wid*32 + it*4 + lt4;
                int token = sSrc[row];
                __half* dst = gdst + row*SLDH + lc8*8;
                if (token>=0){
                    const __half* pg = g_T1g + ((((size_t)(t<<8)+sAV[row])<<9) + ch*128 + lc8*8);
                    const __half* ph = g_T1h + ((((size_t)(t<<8)+sBV[row])<<9) + ch*128 + lc8*8);
                    const __half* pf = g_T1fc + (((size_t)sOC[row]<<9) + ch*128 + lc8*8);
                    #pragma unroll
                    for (int seg=0; seg<2; seg++){
                        int off = seg*64;
                        uint4 va = *(const uint4*)(pg+off);
                        uint4 vb = *(const uint4*)(ph+off);
                        uint4 vf = *(const uint4*)(pf+off);
                        __half2* ha=(__half2*)&va;
                        __half2* hb=(__half2*)&vb;
                        __half2* hf=(__half2*)&vf;
                        uint4 ou; __half2* ho=(__half2*)&ou;
                        #pragma unroll
                        for (int q=0;q<4;q++){
                            __half2 v  = __hadd2(__hadd2(ha[q],hb[q]), hf[q]);
                            __half2 v2 = __hmul2(v,v);
                            __half2 v3 = __hmul2(v2,v);
                            __half2 in2= __hfma2(v3, C0, v);
                            __half2 u  = __hmul2(in2, C1);
                            uint32_t ur = *(uint32_t*)&u, tr;
                            asm("tanh.approx.f16x2 %0, %1;" : "=r"(tr) : "r"(ur));
                            __half2 th = *(__half2*)&tr;
                            __half2 onep = __hadd2(th, ONE);
                            __half2 hv = __hmul2(v, HLF);
                            ho[q] = __hmul2(hv, onep);
                        }
                        *(uint4*)(dst+off) = ou;
                    }
                } else {
                    uint4 z = make_uint4(0,0,0,0);
                    *(uint4*)(dst) = z;
                    *(uint4*)(dst+64) = z;
                }
            }
            BAR_ARRIVE2(1+buf);
        }
    } else {
        // ================= CONSUMER =================
        int cm = wid-4;
        int ctid = cm*32 + lane;
        int grp = lane>>2, tq = lane&3;
        uint32_t aoff  = (uint32_t)((lane&15)*SLDH + (lane>>4)*8)*2;
        uint32_t boff4 = (uint32_t)(((lane&7) + ((lane>>4)<<3))*SLDH + ((lane>>3)&1)*8)*2;
        const __half* Wcp = g_Wch + t*32768;

        #pragma unroll
        for (int j=0;j<8;j++){
            int i = ctid + j*128;
            int row = i>>4, ck = i&15;
            cpa16(wbuf[0] + (uint32_t)(row*SLDH + ck*8)*2, Wcp + row*512 + ck*8);
        }
        cpa_commit();

        float c2[2][8][4];
        #pragma unroll
        for(int mt=0;mt<2;mt++)
            #pragma unroll
            for(int nt=0;nt<8;nt++)
                #pragma unroll
                for(int e=0;e<4;e++) c2[mt][nt][e]=0.f;

        for (int ch=0; ch<4; ch++){
            int buf = ch&1;
            cpa_wait0();
            BAR_SYNC_C();
            BAR_SYNC2(1+buf);
            if (ch<3){
                const __half* src = Wcp + (ch+1)*128;
                #pragma unroll
                for (int j=0;j<8;j++){
                    int i = ctid + j*128;
                    int row = i>>4, ck = i&15;
                    cpa16(wbuf[(ch+1)&1] + (uint32_t)(row*SLDH + ck*8)*2, src + row*512 + ck*8);
                }
                cpa_commit();
            }
            uint32_t bg = gbuf[buf], bw = wbuf[buf];
            #pragma unroll
            for (int kk=0;kk<8;kk++){
                uint32_t af[2][4];
                ldsm4(af[0], bg + aoff + (uint32_t)((cm*32)*SLDH + kk*16)*2);
                ldsm4(af[1], bg + aoff + (uint32_t)((cm*32+16)*SLDH + kk*16)*2);
                #pragma unroll
                for (int ntp=0;ntp<4;ntp++){
                    uint32_t bq[4];
                    ldsm4(bq, bw + boff4 + (uint32_t)((ntp*16)*SLDH + kk*16)*2);
                    mma16(c2[0][2*ntp],   af[0], bq);
                    mma16(c2[1][2*ntp],   af[1], bq);
                    mma16(c2[0][2*ntp+1], af[0], bq+2);
                    mma16(c2[1][2*ntp+1], af[1], bq+2);
                }
            }
            if (ch<2) BAR_ARRIVE2(3+buf);
        }

        float* sH = (float*)sG0;   // [128][66]
        #pragma unroll
        for (int mt=0;mt<2;mt++){
            int row0 = cm*32+mt*16+grp;
            float ga = sGate[row0], gb = sGate[row0+8];
            #pragma unroll
            for (int nt=0;nt<8;nt++){
                int col = nt*8+2*tq;
                sH[row0*66+col]       = fmaxf(ga*c2[mt][nt][0]+sbh1[col],   0.f);
                sH[row0*66+col+1]     = fmaxf(ga*c2[mt][nt][1]+sbh1[col+1], 0.f);
                sH[(row0+8)*66+col]   = fmaxf(gb*c2[mt][nt][2]+sbh1[col],   0.f);
                sH[(row0+8)*66+col+1] = fmaxf(gb*c2[mt][nt][3]+sbh1[col+1], 0.f);
            }
        }
    }
    __syncthreads();
    {
        float* sH = (float*)sG0;
        int row = tid>>1, c0 = (tid&1)*4;
        int token = sSrc[row];
        if (token>=0){
            float acc0=sbh2[c0], acc1=sbh2[c0+1], acc2=sbh2[c0+2], acc3=sbh2[c0+3];
            #pragma unroll 8
            for (int k2=0;k2<64;k2++){
                float hv = sH[row*66+k2];
                acc0 += hv*sWh2[k2*8+c0];
                acc1 += hv*sWh2[k2*8+c0+1];
                acc2 += hv*sWh2[k2*8+c0+2];
                acc3 += hv*sWh2[k2*8+c0+3];
            }
            float* o = outR + (size_t)token*8 + c0;
            o[0] = 1.f/(1.f+__expf(-acc0));
            o[1] = 1.f/(1.f+__expf(-acc1));
            o[2] = 1.f/(1.f+__expf(-acc2));
            o[3] = 1.f/(1.f+__expf(-acc3));
        }
    }
}

// ---------------- launch ----------------
extern "C" void kernel_launch(void* const* d_in, const int* in_sizes, int n_in,
                              void* d_out, int out_size){
    const int *op=nullptr,*a=nullptr,*b=nullptr,*c=nullptr;
    const float *oe=nullptr,*Win=nullptr,*bin=nullptr,*Wr=nullptr,*W1=nullptr,*W2=nullptr;
    const float *Wh1=nullptr,*bh1=nullptr,*Wh2=nullptr,*bh2=nullptr;
    int nb_=0, nw=0;
    for (int i=0;i<n_in;i++){
        int s = in_sizes[i]; void* p = (void*)d_in[i];
        switch(s){
            case BTOK:
                if(nb_==0) op=(const int*)p; else if(nb_==1) a=(const int*)p;
                else if(nb_==2) b=(const int*)p; else c=(const int*)p;
                nb_++; break;
            case 256:  oe=(const float*)p; break;
            case 6272: Win=(const float*)p; break;
            case 128:  bin=(const float*)p; break;
            case 2048: Wr=(const float*)p; break;
            case 1048576: if(nw==0) W1=(const float*)p; else W2=(const float*)p; nw++; break;
            case 8192: Wh1=(const float*)p; break;
            case 64:   bh1=(const float*)p; break;
            case 512:  Wh2=(const float*)p; break;
            case 8:    bh2=(const float*)p; break;
            default: break;
        }
    }
    float* out = (float*)d_out;
    int smem = 384*SLDH*2;
    cudaFuncSetAttribute(k_ffn, cudaFuncAttributeMaxDynamicSharedMemorySize, smem);

    k_lt2<<<1,256>>>(oe,Wr,Win,bin);
    k_scalep<<<512,256>>>(W1,W2);
    k_quant<<<256,256>>>(W1,W2);
    k_u<<<256,256>>>(Win,bin);
    k_prep<<<528,256>>>(Wh1,oe);
    k_route<<<BTOK/256,256>>>(op,a,b,c,out + (size_t)BTOK*8);
    k_part<<<1,256>>>(out + (size_t)BTOK*9);
    k_ffn<<<MAXBLK,256,smem>>>(op,a,b,c,bh1,Wh2,bh2,out);
}

// round 16
// speedup vs baseline: 1.1470x; 1.0167x over previous
#include <cuda_runtime.h>
#include <cuda_fp16.h>
#include <cstdint>

#define BTOK 262144
#define DM 128
#define DFF 512
#define NT 16
#define NOPS 8
#define EMB 32
#define MROWS 128
#define SLDH 136
#define MAXBLK (BTOK/MROWS + NT)
#define TSTR (BTOK + 128)

// ---------------- device scratch ----------------
__device__ float g_Lf[NOPS*NT];
__device__ float g_Lg[256*NT];
__device__ float g_Lh[256*NT];
__device__ float g_Lc[NT];
__device__ float g_Lb[NT];
__device__ double g_sabs[32];
__device__ double g_res[2];
__device__ __half g_W1h[NT*DFF*DM];   // [t][n(dff)][k(d)]
__device__ __half g_W2h[NT*DM*DFF];   // [t][nn(d)][kk(dff)]
__device__ __half g_Wch[NT*64*DFF];   // [t][n(64)][k(dff)] = s2 * W2q @ Wh1
__device__ float  g_U[NT*50*DFF];     // [t][f(49)+bias][n(dff)]
__device__ __half g_T1g[NT*256*DFF];
__device__ __half g_T1h[NT*256*DFF];
__device__ __half g_T1fc[NT*NOPS*2*DFF];
__device__ double g_sumP[NT];
__device__ int g_fill[NT];
__device__ int g_nblocks;
__device__ float g_gate[BTOK];
__device__ int g_src[NT*TSTR];
__device__ int g_bmT[MAXBLK];
__device__ int g_bmR[MAXBLK];

// ---------------- helpers ----------------
__device__ __forceinline__ uint32_t smem_u32(const void* p){
    uint32_t a;
    asm("{ .reg .u64 t; cvta.to.shared.u64 t, %1; cvt.u32.u64 %0, t; }":"=r"(a):"l"(p));
    return a;
}
__device__ __forceinline__ void ldsm4(uint32_t* r, uint32_t addr){
    asm volatile("ldmatrix.sync.aligned.m8n8.x4.shared.b16 {%0,%1,%2,%3}, [%4];"
        : "=r"(r[0]),"=r"(r[1]),"=r"(r[2]),"=r"(r[3]) : "r"(addr));
}
__device__ __forceinline__ void mma16(float* c, const uint32_t* a, const uint32_t* b){
    asm volatile("mma.sync.aligned.m16n8k16.row.col.f32.f16.f16.f32 "
        "{%0,%1,%2,%3},{%4,%5,%6,%7},{%8,%9},{%0,%1,%2,%3};"
        : "+f"(c[0]),"+f"(c[1]),"+f"(c[2]),"+f"(c[3])
        : "r"(a[0]),"r"(a[1]),"r"(a[2]),"r"(a[3]),"r"(b[0]),"r"(b[1]));
}
__device__ __forceinline__ __half2 h2pack(float a, float b){
    return __floats2half2_rn(a, b);
}
__device__ __forceinline__ void cpa16(uint32_t dst, const void* src){
    asm volatile("cp.async.cg.shared.global [%0], [%1], 16;" :: "r"(dst),"l"(src):"memory");
}
__device__ __forceinline__ void cpa_commit(){
    asm volatile("cp.async.commit_group;":::"memory");
}
__device__ __forceinline__ void cpa_wait0(){
    asm volatile("cp.async.wait_group 0;":::"memory");
}
#define BAR_SYNC2(id)   asm volatile("bar.sync %0, 256;"   :: "r"(id) : "memory")
#define BAR_ARRIVE2(id) asm volatile("bar.arrive %0, 256;" :: "r"(id) : "memory")
#define BAR_SYNC_C()    asm volatile("bar.sync 5, 128;"    ::: "memory")

// ---------------- k_lt2: init + router logit tables (1 block) ----------------
__global__ void k_lt2(const float* __restrict__ oe, const float* __restrict__ Wr,
                      const float* __restrict__ Win, const float* __restrict__ bin){
    __shared__ float WR[50*16];
    int tid = threadIdx.x;
    if (tid < NT){ g_sumP[tid]=0.0; g_fill[tid]=0; }
    if (tid < 32) g_sabs[tid]=0.0;
    if (tid < 2)  g_res[tid]=0.0;
    for (int o = tid; o < 800; o += 256){
        int f = o>>4, tt = o&15;
        const float* src = (f<49) ? (Win + f*DM) : bin;
        float acc = 0.f;
        #pragma unroll 8
        for (int d=0; d<DM; d++) acc += src[d]*Wr[d*NT+tt];
        WR[o] = acc;
    }
    __syncthreads();
    for (int o=tid; o<NOPS*NT; o+=256){
        int opv = o>>4, tt = o&15;
        float acc = 0.f;
        #pragma unroll 8
        for (int j=0;j<EMB;j++) acc += oe[opv*EMB+j]*WR[j*16+tt];
        g_Lf[o] = acc;
    }
    for (int o=tid; o<4096; o+=256){
        int av = o>>4, tt = o&15;
        float a1=0.f, a2=0.f;
        #pragma unroll
        for (int i=0;i<8;i++) if ((av>>i)&1){ a1 += WR[(32+i)*16+tt]; a2 += WR[(40+i)*16+tt]; }
        g_Lg[o]=a1; g_Lh[o]=a2;
    }
    if (tid<16){ g_Lc[tid]=WR[48*16+tid]; g_Lb[tid]=WR[49*16+tid]; }
}

// ---------------- k_scalep ----------------
__global__ void k_scalep(const float* __restrict__ W1, const float* __restrict__ W2){
    __shared__ double red[256];
    int tile = blockIdx.x >> 4;
    int sub  = blockIdx.x & 15;
    const float* W = (tile < 16 ? W1 + tile*65536 : W2 + (tile-16)*65536) + sub*4096;
    const float4* W4 = (const float4*)W;
    double s0=0.0,s1=0.0,s2=0.0,s3=0.0;
    float4 v0 = W4[threadIdx.x];
    float4 v1 = W4[threadIdx.x + 256];
    float4 v2 = W4[threadIdx.x + 512];
    float4 v3 = W4[threadIdx.x + 768];
    s0 += (double)(fabsf(v0.x)+fabsf(v0.y)+fabsf(v0.z)+fabsf(v0.w));
    s1 += (double)(fabsf(v1.x)+fabsf(v1.y)+fabsf(v1.z)+fabsf(v1.w));
    s2 += (double)(fabsf(v2.x)+fabsf(v2.y)+fabsf(v2.z)+fabsf(v2.w));
    s3 += (double)(fabsf(v3.x)+fabsf(v3.y)+fabsf(v3.z)+fabsf(v3.w));
    red[threadIdx.x]=(s0+s1)+(s2+s3); __syncthreads();
    for (int o=128;o;o>>=1){ if(threadIdx.x<o) red[threadIdx.x]+=red[threadIdx.x+o]; __syncthreads(); }
    if (!threadIdx.x) atomicAdd(&g_sabs[tile], red[0]);
}

// ---------------- k_quant ----------------
__global__ void k_quant(const float* __restrict__ W1, const float* __restrict__ W2){
    __shared__ __half sh[64*130];
    __shared__ double red[256];
    int b = blockIdx.x, tid = threadIdx.x;
    double racc = 0.0;
    if (b < 128){
        int t = b>>3, n0 = (b&7)*64;
        float s = (float)(g_sabs[t]/65536.0);
        const float* src = W1 + t*65536;
        #pragma unroll
        for (int j=0;j<32;j++){
            int i = tid + j*256;
            int k = i>>6, nx = i&63;
            float w = src[k*512 + n0 + nx];
            float aw = fabsf(w);
            bool nz = aw > 0.7f*s;
            float q = nz ? (w>0.f?1.f:-1.f) : 0.f;
            racc += (double)(nz ? fabsf(aw - s) : aw);
            sh[nx*130 + k] = __float2half(q);
        }
        __syncthreads();
        __half* dst = g_W1h + t*65536 + n0*128;
        #pragma unroll
        for (int j=0;j<32;j++){
            int i = tid + j*256;
            int n = i>>7, k = i&127;
            dst[n*128 + k] = sh[n*130 + k];
        }
        red[tid]=racc; __syncthreads();
        for(int o=128;o;o>>=1){ if(tid<o) red[tid]+=red[tid+o]; __syncthreads(); }
        if (!tid) atomicAdd(&g_res[0], red[0]);
    } else {
        int bb = b-128;
        int t = bb>>3, kk0 = (bb&7)*64;
        float s = (float)(g_sabs[16+t]/65536.0);
        const float* src = W2 + t*65536;
        #pragma unroll
        for (int j=0;j<32;j++){
            int i = tid + j*256;
            int kk = i>>7, nn = i&127;
            float w = src[(kk0+kk)*128 + nn];
            float aw = fabsf(w);
            bool nz = aw > 0.7f*s;
            float q = nz ? (w>0.f?1.f:-1.f) : 0.f;
            racc += (double)(nz ? fabsf(aw - s) : aw);
            sh[kk*130 + nn] = __float2half(q);
        }
        __syncthreads();
        __half* dst = g_W2h + t*65536 + kk0;
        #pragma unroll
        for (int j=0;j<32;j++){
            int i = tid + j*256;
            int nn = i>>6, kx = i&63;
            dst[nn*512 + kx] = sh[kx*130 + nn];
        }
        red[tid]=racc; __syncthreads();
        for(int o=128;o;o>>=1){ if(tid<o) red[tid]+=red[tid+o]; __syncthreads(); }
        if (!tid) atomicAdd(&g_res[1], red[0]);
    }
}

// ---------------- k_u: U = [Win;bin] @ W1q^T, fully conflict-free ----------------
// grid 256: t = b>>4, n0 = (b&15)*32 ; sWd stride 33
__global__ void k_u(const float* __restrict__ Win, const float* __restrict__ bin){
    __shared__ float sWin[50*128];     // 25.6KB
    __shared__ float sWd[128*33];      // [d][n] padded, 16.9KB
    int b = blockIdx.x, tid = threadIdx.x;
    int t = b>>4, n0 = (b&15)*32;
    for (int i=tid; i<6400; i+=256) sWin[i] = (i<6272) ? Win[i] : bin[i-6272];
    const __half* src = g_W1h + t*65536 + n0*128;
    for (int i=tid; i<4096; i+=256){
        int n = i>>7, d = i&127;
        sWd[d*33+n] = __half2float(src[i]);
    }
    __syncthreads();
    for (int o=tid; o<1600; o+=256){
        int f = o>>5, n = o&31;
        const float* wf = sWin + f*128;
        float acc = 0.f;
        #pragma unroll 16
        for (int d=0; d<128; d++)
            acc += wf[d]*sWd[d*33+n];
        g_U[(t*50+f)*512 + n0 + n] = acc;
    }
}

// ---------------- k_prep: merged tg(0-255) | wc(256-511) | tfc(512-527) ----------------
__global__ void k_prep(const float* __restrict__ Wh1, const float* __restrict__ oe){
    __shared__ char buf[41984];
    int b = blockIdx.x, tid = threadIdx.x;
    if (b < 256){
        float* sU = (float*)buf;
        int t = b>>4, which = (b>>3)&1, av0 = (b&7)*32;
        for (int i=tid; i<4096; i+=256)
            sU[i] = g_U[(t*50 + 32 + which*8 + (i>>9))*512 + (i&511)];
        float s1 = (float)(g_sabs[t]/65536.0);
        __half* dst = (which ? g_T1h : g_T1g) + ((size_t)t<<17) + (size_t)av0*512;
        __syncthreads();
        for (int o=tid; o<16384; o+=256){
            int av = av0 + (o>>9), n = o&511;
            float acc = 0.f;
            #pragma unroll
            for (int i=0;i<8;i++) if ((av>>i)&1) acc += sU[i*512+n];
            dst[o] = __float2half(s1*acc);
        }
    } else if (b < 512){
        float* sWh1 = (float*)buf;
        __half* sW2 = (__half*)(buf + 32768);
        int bb = b-256;
        int t = bb>>4, k0 = (bb&15)*32;
        float s2 = (float)(g_sabs[16+t]/65536.0);
        #pragma unroll
        for (int j=0;j<32;j++) sWh1[tid + j*256] = Wh1[tid + j*256];
        const __half* W2p = g_W2h + t*65536 + k0;
        #pragma unroll
        for (int j=0;j<16;j++){
            int i = tid + j*256;
            int d = i>>5, kx = i&31;
            sW2[d*32 + kx] = W2p[d*512 + kx];
        }
        __syncthreads();
        #pragma unroll
        for (int j=0;j<8;j++){
            int o = tid + j*256;
            int n = o&63, kx = o>>6;
            float acc = 0.f;
            #pragma unroll 8
            for (int d=0; d<128; d++)
                acc += __half2float(sW2[d*32 + kx]) * sWh1[d*64 + n];
            g_Wch[t*32768 + n*512 + k0 + kx] = __float2half(s2*acc);
        }
    } else {
        int t = b-512;
        float s1 = (float)(g_sabs[t]/65536.0);
        for (int o=tid; o<8192; o+=256){
            int n = o&511, cc = (o>>9)&1, opv = o>>10;
            float acc = g_U[(t*50+49)*512+n];
            if (cc) acc += g_U[(t*50+48)*512+n];
            #pragma unroll 8
            for (int j=0;j<32;j++)
                acc += oe[opv*32+j] * g_U[(t*50+j)*512+n];
            g_T1fc[t*8192 + o] = __float2half(s1*acc);
        }
    }
}

// ---------------- k_route ----------------
__global__ void k_route(const int* __restrict__ op, const int* __restrict__ a,
                        const int* __restrict__ b, const int* __restrict__ c,
                        float* __restrict__ outIdx){
    __shared__ float sLf[NOPS*NT], sLg[256*NT], sLh[256*NT], sLc[NT], sLb[NT];
    __shared__ float sP[NT]; __shared__ int sC[NT]; __shared__ int sBase[NT];
    int tid = threadIdx.x;
    int lane = tid & 31;
    for (int i=tid;i<256*NT;i+=256){ sLg[i]=g_Lg[i]; sLh[i]=g_Lh[i]; }
    for (int i=tid;i<NOPS*NT;i+=256) sLf[i]=g_Lf[i];
    if (tid<NT){ sLc[tid]=g_Lc[tid]; sLb[tid]=g_Lb[tid]; sP[tid]=0.f; sC[tid]=0; }
    __syncthreads();
    int i = blockIdx.x*256+tid;
    int opv=op[i], av=a[i], bv=b[i]; float cv=(float)c[i];
    float l[NT]; float mx=-1e30f; int best=0;
    #pragma unroll
    for (int t=0;t<NT;t++){
        float v = sLf[opv*NT+t]+sLg[av*NT+t]+sLh[bv*NT+t]+cv*sLc[t]+sLb[t];
        l[t]=v;
        if (v>mx){mx=v;best=t;}
    }
    float den=0.f;
    #pragma unroll
    for (int t=0;t<NT;t++){ l[t]=__expf(l[t]-mx); den+=l[t]; }
    float inv = 1.f/den;
    #pragma unroll
    for (int t=0;t<NT;t++){
        float v = l[t]*inv;
        #pragma unroll
        for (int o=16;o;o>>=1) v += __shfl_xor_sync(0xffffffffu, v, o);
        if (lane==0) atomicAdd(&sP[t], v);
    }
    int rank = atomicAdd(&sC[best], 1);
    g_gate[i]=inv; outIdx[i]=(float)best;
    __syncthreads();
    if (tid<NT){
        sBase[tid] = atomicAdd(&g_fill[tid], sC[tid]);
        atomicAdd(&g_sumP[tid], (double)sP[tid]);
    }
    __syncthreads();
    g_src[best*TSTR + sBase[best] + rank] = i;
}

// ---------------- k_part (+ fused aux) ----------------
__global__ void k_part(float* __restrict__ aux){
    __shared__ int pc[NT], po_[NT];
    int tid=threadIdx.x;
    if (tid<NT) pc[tid] = g_fill[tid];
    __syncthreads();
    if (tid==0){
        int nb=0;
        for (int t=0;t<NT;t++){ po_[t]=nb; nb += (pc[t]+MROWS-1)/MROWS; }
        g_nblocks = nb;
    }
    if (tid==32){
        double sp=0.0, cp[4]={0,0,0,0};
        for (int t=0;t<NT;t++){
            double frac = (double)g_fill[t]/(double)BTOK;
            double mp = g_sumP[t]/(double)BTOK;
            sp += frac*mp;
            cp[t>>2] += mp;
        }
        double sparsity = 16.0*sp;
        double tern = g_res[0]/1048576.0 + g_res[1]/1048576.0;
        double divv = 0.0;
        for (int i=0;i<4;i++) divv += cp[i]*log(cp[i]+1e-9);
        aux[0] = (float)(0.01*tern + 0.005*sparsity + 0.01*divv);
    }
    __syncthreads();
    for (int t=0;t<NT;t++){
        int bl = (pc[t]+MROWS-1)/MROWS;
        for (int bi=tid; bi<bl; bi+=256){ g_bmT[po_[t]+bi]=t; g_bmR[po_[t]+bi]=t*TSTR + bi*MROWS; }
        int cnt=pc[t]; int pad = bl*MROWS;
        for (int p=cnt+tid; p<pad; p+=256) g_src[t*TSTR+p] = -1;
    }
}

// ---------------- k_ffn: warp-specialized producer/consumer ----------------
__global__ void __launch_bounds__(256,2) k_ffn(
    const int* __restrict__ op, const int* __restrict__ aIn,
    const int* __restrict__ bIn, const int* __restrict__ cIn,
    const float* __restrict__ bh1,
    const float* __restrict__ Wh2, const float* __restrict__ bh2,
    float* __restrict__ outR)
{
    extern __shared__ __half sm[];
    __half* sG0 = sm;
    __half* sG1 = sm + 128*SLDH;
    __half* sW0 = sm + 256*SLDH;
    __half* sW1 = sW0 + 64*SLDH;
    __shared__ float sGate[MROWS];
    __shared__ int   sSrc[MROWS];
    __shared__ int   sAV[MROWS], sBV[MROWS], sOC[MROWS];
    __shared__ float sWh2[512], sbh1[64], sbh2[8];

    int bid = blockIdx.x;
    if (bid >= g_nblocks) return;
    int t  = g_bmT[bid], r0 = g_bmR[bid];
    int tid = threadIdx.x;
    int wid = tid>>5, lane = tid&31;

    uint32_t gbuf[2] = { smem_u32(sG0), smem_u32(sG1) };
    uint32_t wbuf[2] = { smem_u32(sW0), smem_u32(sW1) };

    if (wid < 4){
        // ================= PRODUCER =================
        // gather this warp's own 32 rows (row == tid for tid<128)
        {
            int token = g_src[r0+tid];
            sSrc[tid] = token;
            if (token>=0){
                sGate[tid] = g_gate[token];
                sAV[tid] = aIn[token];
                sBV[tid] = bIn[token];
                sOC[tid] = (t*8 + op[token])*2 + cIn[token];
            } else {
                sGate[tid]=0.f; sAV[tid]=0; sBV[tid]=0; sOC[tid]=t*16;
            }
        }
        __syncwarp();
        int lt4 = lane>>3, lc8 = lane&7;
        const __half2 C0 = __floats2half2_rn(0.044715f, 0.044715f);
        const __half2 C1 = __floats2half2_rn(0.7978845608f, 0.7978845608f);
        const __half2 ONE = __floats2half2_rn(1.f, 1.f);
        const __half2 HLF = __floats2half2_rn(0.5f, 0.5f);
        for (int ch=0; ch<4; ch++){
            int buf = ch&1;
            if (ch>=2) BAR_SYNC2(3+buf);
            __half* gdst = buf ? sG1 : sG0;
            #pragma unroll
            for (int it=0; it<8; it++){
                int row = wid*32 + it*4 + lt4;
                int token = sSrc[row];
                __half* dst = gdst + row*SLDH + lc8*8;
                if (token>=0){
                    const __half* pg = g_T1g + ((((size_t)(t<<8)+sAV[row])<<9) + ch*128 + lc8*8);
                    const __half* ph = g_T1h + ((((size_t)(t<<8)+sBV[row])<<9) + ch*128 + lc8*8);
                    const __half* pf = g_T1fc + (((size_t)sOC[row]<<9) + ch*128 + lc8*8);
                    #pragma unroll
                    for (int seg=0; seg<2; seg++){
                        int off = seg*64;
                        uint4 va = *(const uint4*)(pg+off);
                        uint4 vb = *(const uint4*)(ph+off);
                        uint4 vf = *(const uint4*)(pf+off);
                        __half2* ha=(__half2*)&va;
                        __half2* hb=(__half2*)&vb;
                        __half2* hf=(__half2*)&vf;
                        uint4 ou; __half2* ho=(__half2*)&ou;
                        #pragma unroll
                        for (int q=0;q<4;q++){
                            __half2 v  = __hadd2(__hadd2(ha[q],hb[q]), hf[q]);
                            __half2 v2 = __hmul2(v,v);
                            __half2 v3 = __hmul2(v2,v);
                            __half2 in2= __hfma2(v3, C0, v);
                            __half2 u  = __hmul2(in2, C1);
                            uint32_t ur = *(uint32_t*)&u, tr;
                            asm("tanh.approx.f16x2 %0, %1;" : "=r"(tr) : "r"(ur));
                            __half2 th = *(__half2*)&tr;
                            __half2 onep = __hadd2(th, ONE);
                            __half2 hv = __hmul2(v, HLF);
                            ho[q] = __hmul2(hv, onep);
                        }
                        *(uint4*)(dst+off) = ou;
                    }
                } else {
                    uint4 z = make_uint4(0,0,0,0);
                    *(uint4*)(dst) = z;
                    *(uint4*)(dst+64) = z;
                }
            }
            BAR_ARRIVE2(1+buf);
        }
    } else {
        // ================= CONSUMER =================
        int cm = wid-4;
        int ctid = cm*32 + lane;
        int grp = lane>>2, tq = lane&3;
        uint32_t aoff  = (uint32_t)((lane&15)*SLDH + (lane>>4)*8)*2;
        uint32_t boff4 = (uint32_t)(((lane&7) + ((lane>>4)<<3))*SLDH + ((lane>>3)&1)*8)*2;
        const __half* Wcp = g_Wch + t*32768;

        // small-param loads (consumer half only)
        if (ctid < 128){
            sWh2[ctid]=Wh2[ctid]; sWh2[128+ctid]=Wh2[128+ctid];
            sWh2[256+ctid]=Wh2[256+ctid]; sWh2[384+ctid]=Wh2[384+ctid];
        }
        if (ctid<64) sbh1[ctid]=bh1[ctid];
        if (ctid<8)  sbh2[ctid]=bh2[ctid];

        #pragma unroll
        for (int j=0;j<8;j++){
            int i = ctid + j*128;
            int row = i>>4, ck = i&15;
            cpa16(wbuf[0] + (uint32_t)(row*SLDH + ck*8)*2, Wcp + row*512 + ck*8);
        }
        cpa_commit();

        float c2[2][8][4];
        #pragma unroll
        for(int mt=0;mt<2;mt++)
            #pragma unroll
            for(int nt=0;nt<8;nt++)
                #pragma unroll
                for(int e=0;e<4;e++) c2[mt][nt][e]=0.f;

        for (int ch=0; ch<4; ch++){
            int buf = ch&1;
            cpa_wait0();
            BAR_SYNC_C();
            BAR_SYNC2(1+buf);
            if (ch<3){
                const __half* src = Wcp + (ch+1)*128;
                #pragma unroll
                for (int j=0;j<8;j++){
                    int i = ctid + j*128;
                    int row = i>>4, ck = i&15;
                    cpa16(wbuf[(ch+1)&1] + (uint32_t)(row*SLDH + ck*8)*2, src + row*512 + ck*8);
                }
                cpa_commit();
            }
            uint32_t bg = gbuf[buf], bw = wbuf[buf];
            #pragma unroll
            for (int kk=0;kk<8;kk++){
                uint32_t af[2][4];
                ldsm4(af[0], bg + aoff + (uint32_t)((cm*32)*SLDH + kk*16)*2);
                ldsm4(af[1], bg + aoff + (uint32_t)((cm*32+16)*SLDH + kk*16)*2);
                #pragma unroll
                for (int ntp=0;ntp<4;ntp++){
                    uint32_t bq[4];
                    ldsm4(bq, bw + boff4 + (uint32_t)((ntp*16)*SLDH + kk*16)*2);
                    mma16(c2[0][2*ntp],   af[0], bq);
                    mma16(c2[1][2*ntp],   af[1], bq);
                    mma16(c2[0][2*ntp+1], af[0], bq+2);
                    mma16(c2[1][2*ntp+1], af[1], bq+2);
                }
            }
            if (ch<2) BAR_ARRIVE2(3+buf);
        }

        float* sH = (float*)sG0;   // [128][66]
        #pragma unroll
        for (int mt=0;mt<2;mt++){
            int row0 = cm*32+mt*16+grp;
            float ga = sGate[row0], gb = sGate[row0+8];
            #pragma unroll
            for (int nt=0;nt<8;nt++){
                int col = nt*8+2*tq;
                sH[row0*66+col]       = fmaxf(ga*c2[mt][nt][0]+sbh1[col],   0.f);
                sH[row0*66+col+1]     = fmaxf(ga*c2[mt][nt][1]+sbh1[col+1], 0.f);
                sH[(row0+8)*66+col]   = fmaxf(gb*c2[mt][nt][2]+sbh1[col],   0.f);
                sH[(row0+8)*66+col+1] = fmaxf(gb*c2[mt][nt][3]+sbh1[col+1], 0.f);
            }
        }
    }
    __syncthreads();
    {
        float* sH = (float*)sG0;
        int row = tid>>1, c0 = (tid&1)*4;
        int token = sSrc[row];
        if (token>=0){
            float acc0=sbh2[c0], acc1=sbh2[c0+1], acc2=sbh2[c0+2], acc3=sbh2[c0+3];
            #pragma unroll 8
            for (int k2=0;k2<64;k2++){
                float hv = sH[row*66+k2];
                acc0 += hv*sWh2[k2*8+c0];
                acc1 += hv*sWh2[k2*8+c0+1];
                acc2 += hv*sWh2[k2*8+c0+2];
                acc3 += hv*sWh2[k2*8+c0+3];
            }
            float* o = outR + (size_t)token*8 + c0;
            o[0] = 1.f/(1.f+__expf(-acc0));
            o[1] = 1.f/(1.f+__expf(-acc1));
            o[2] = 1.f/(1.f+__expf(-acc2));
            o[3] = 1.f/(1.f+__expf(-acc3));
        }
    }
}

// ---------------- launch ----------------
extern "C" void kernel_launch(void* const* d_in, const int* in_sizes, int n_in,
                              void* d_out, int out_size){
    const int *op=nullptr,*a=nullptr,*b=nullptr,*c=nullptr;
    const float *oe=nullptr,*Win=nullptr,*bin=nullptr,*Wr=nullptr,*W1=nullptr,*W2=nullptr;
    const float *Wh1=nullptr,*bh1=nullptr,*Wh2=nullptr,*bh2=nullptr;
    int nb_=0, nw=0;
    for (int i=0;i<n_in;i++){
        int s = in_sizes[i]; void* p = (void*)d_in[i];
        switch(s){
            case BTOK:
                if(nb_==0) op=(const int*)p; else if(nb_==1) a=(const int*)p;
                else if(nb_==2) b=(const int*)p; else c=(const int*)p;
                nb_++; break;
            case 256:  oe=(const float*)p; break;
            case 6272: Win=(const float*)p; break;
            case 128:  bin=(const float*)p; break;
            case 2048: Wr=(const float*)p; break;
            case 1048576: if(nw==0) W1=(const float*)p; else W2=(const float*)p; nw++; break;
            case 8192: Wh1=(const float*)p; break;
            case 64:   bh1=(const float*)p; break;
            case 512:  Wh2=(const float*)p; break;
            case 8:    bh2=(const float*)p; break;
            default: break;
        }
    }
    float* out = (float*)d_out;
    int smem = 384*SLDH*2;
    cudaFuncSetAttribute(k_ffn, cudaFuncAttributeMaxDynamicSharedMemorySize, smem);

    k_lt2<<<1,256>>>(oe,Wr,Win,bin);
    k_scalep<<<512,256>>>(W1,W2);
    k_quant<<<256,256>>>(W1,W2);
    k_u<<<256,256>>>(Win,bin);
    k_prep<<<528,256>>>(Wh1,oe);
    k_route<<<BTOK/256,256>>>(op,a,b,c,out + (size_t)BTOK*8);
    k_part<<<1,256>>>(out + (size_t)BTOK*9);
    k_ffn<<<MAXBLK,256,smem>>>(op,a,b,c,bh1,Wh2,bh2,out);
}